// round 1
// baseline (speedup 1.0000x reference)
#include <cuda_runtime.h>
#include <math.h>

// Problem constants
#define T_ 512
#define E_ 8
#define H_ 2048
#define I_ 5632
#define A_ (2 * T_)   // 1024 token-expert assignments (top_k = 2)

// ---------------- scratch (device globals; no allocation allowed) ----------------
__device__ float g_act[(size_t)A_ * I_];   // SwiGLU activations per assignment [1024, 5632]
__device__ float g_y[(size_t)A_ * H_];     // down-proj outputs per assignment [1024, 2048]
__device__ int   g_perm[A_];               // assignment ids grouped by expert
__device__ int   g_offs[E_ + 1];           // expert segment offsets into g_perm
__device__ float g_aw[A_];                 // renormalized top-2 weights, indexed by a = 2*t + k

// ---------------- routing: softmax -> top2 -> renorm -> deterministic bucketing ---
__global__ void route_kernel(const float* __restrict__ logits) {
    __shared__ unsigned char s_e[A_];
    __shared__ int s_cnt[E_];
    __shared__ int s_off[E_ + 1];

    int t = threadIdx.x;   // 512 threads, one per token
    if (t < E_) s_cnt[t] = 0;
    __syncthreads();

    float l[E_];
#pragma unroll
    for (int e = 0; e < E_; e++) l[e] = logits[t * E_ + e];

    // argmax (ties -> lowest index, matching jax.lax.top_k)
    int e0 = 0;
#pragma unroll
    for (int e = 1; e < E_; e++) if (l[e] > l[e0]) e0 = e;
    // second argmax
    int e1 = (e0 == 0) ? 1 : 0;
#pragma unroll
    for (int e = 0; e < E_; e++) if (e != e0 && l[e] > l[e1]) e1 = e;

    // softmax over all experts then renormalize over top-2 == e^l0/(e^l0+e^l1)
    float p1 = __expf(l[e1] - l[e0]);
    float inv = 1.0f / (1.0f + p1);
    g_aw[2 * t + 0] = inv;
    g_aw[2 * t + 1] = p1 * inv;

    s_e[2 * t + 0] = (unsigned char)e0;
    s_e[2 * t + 1] = (unsigned char)e1;
    atomicAdd(&s_cnt[e0], 1);
    atomicAdd(&s_cnt[e1], 1);
    __syncthreads();

    if (t == 0) {
        int acc = 0;
        for (int e = 0; e < E_; e++) { s_off[e] = acc; acc += s_cnt[e]; }
        s_off[E_] = acc;  // == A_
        for (int e = 0; e <= E_; e++) g_offs[e] = s_off[e];
    }
    __syncthreads();

    // stable rank within expert (deterministic counting sort)
#pragma unroll
    for (int k = 0; k < 2; k++) {
        int a = 2 * t + k;
        int e = s_e[a];
        int rank = 0;
        for (int b = 0; b < a; b++) rank += (s_e[b] == e) ? 1 : 0;
        g_perm[s_off[e] + rank] = a;
    }
}

// ---------------- GEMM1: act[a, i] = silu(x@Wg^T) * (x@Wu^T), gathered per expert ---
// Tile: 64 (M, assignments) x 64 (N, intermediate i) x 16 (K, hidden). Dual N-tile (gate+up).
__global__ __launch_bounds__(256) void gemm1_kernel(
    const float* __restrict__ x, const float* __restrict__ w13)
{
    int e = blockIdx.z;
    int base = g_offs[e];
    int cnt  = g_offs[e + 1] - base;
    int m0 = blockIdx.y * 64;
    if (m0 >= cnt) return;          // uniform early exit
    int i0 = blockIdx.x * 64;

    __shared__ float Xs[16][64];
    __shared__ float Gs[16][64];
    __shared__ float Us[16][64];

    int tid = threadIdx.x;
    int ty = tid >> 4, tx = tid & 15;     // compute mapping: 16x16 threads, 4x4 micro-tile
    int lr = tid >> 2;                    // load mapping: row in tile 0..63
    int lk = (tid & 3) * 4;               // k sub-offset 0,4,8,12

    int mr = m0 + lr;
    bool av = mr < cnt;
    int tok = av ? (g_perm[base + mr] >> 1) : 0;

    const float* xp = x + (size_t)tok * H_ + lk;
    const float* gp = w13 + ((size_t)e * 2 * I_ + (size_t)(i0 + lr)) * H_ + lk;
    const float* up = gp + (size_t)I_ * H_;

    float cg[4][4] = {}, cu[4][4] = {};

    for (int k0 = 0; k0 < H_; k0 += 16) {
        float4 xa = av ? *(const float4*)xp : make_float4(0.f, 0.f, 0.f, 0.f);
        float4 ga = *(const float4*)gp;
        float4 ua = *(const float4*)up;
        xp += 16; gp += 16; up += 16;

        __syncthreads();   // protect previous iteration's reads
        Xs[lk + 0][lr] = xa.x; Xs[lk + 1][lr] = xa.y; Xs[lk + 2][lr] = xa.z; Xs[lk + 3][lr] = xa.w;
        Gs[lk + 0][lr] = ga.x; Gs[lk + 1][lr] = ga.y; Gs[lk + 2][lr] = ga.z; Gs[lk + 3][lr] = ga.w;
        Us[lk + 0][lr] = ua.x; Us[lk + 1][lr] = ua.y; Us[lk + 2][lr] = ua.z; Us[lk + 3][lr] = ua.w;
        __syncthreads();

#pragma unroll
        for (int kk = 0; kk < 16; kk++) {
            float4 a4 = *(const float4*)&Xs[kk][ty * 4];
            float4 g4 = *(const float4*)&Gs[kk][tx * 4];
            float4 u4 = *(const float4*)&Us[kk][tx * 4];
            float aa[4] = {a4.x, a4.y, a4.z, a4.w};
            float gb[4] = {g4.x, g4.y, g4.z, g4.w};
            float ub[4] = {u4.x, u4.y, u4.z, u4.w};
#pragma unroll
            for (int i2 = 0; i2 < 4; i2++)
#pragma unroll
                for (int j = 0; j < 4; j++) {
                    cg[i2][j] += aa[i2] * gb[j];
                    cu[i2][j] += aa[i2] * ub[j];
                }
        }
    }

    // epilogue: SwiGLU, write act
#pragma unroll
    for (int i2 = 0; i2 < 4; i2++) {
        int m = m0 + ty * 4 + i2;
        if (m < cnt) {
            float4 o;
            float* po = (float*)&o;
#pragma unroll
            for (int j = 0; j < 4; j++) {
                float g = cg[i2][j];
                float s = g / (1.0f + __expf(-g));   // silu
                po[j] = s * cu[i2][j];
            }
            *(float4*)&g_act[(size_t)(base + m) * I_ + (size_t)(i0 + tx * 4)] = o;
        }
    }
}

// ---------------- GEMM2: y[a, h] = act[a, :] @ w2[e]^T ----------------
__global__ __launch_bounds__(256) void gemm2_kernel(const float* __restrict__ w2)
{
    int e = blockIdx.z;
    int base = g_offs[e];
    int cnt  = g_offs[e + 1] - base;
    int m0 = blockIdx.y * 64;
    if (m0 >= cnt) return;
    int h0 = blockIdx.x * 64;

    __shared__ float As[16][64];
    __shared__ float Bs[16][64];

    int tid = threadIdx.x;
    int ty = tid >> 4, tx = tid & 15;
    int lr = tid >> 2;
    int lk = (tid & 3) * 4;

    int mr = m0 + lr;
    bool av = mr < cnt;
    const float* ap = g_act + (size_t)(base + (av ? mr : 0)) * I_ + lk;
    const float* bp = w2 + ((size_t)e * H_ + (size_t)(h0 + lr)) * I_ + lk;

    float c[4][4] = {};

    for (int k0 = 0; k0 < I_; k0 += 16) {
        float4 aa = av ? *(const float4*)ap : make_float4(0.f, 0.f, 0.f, 0.f);
        float4 bb = *(const float4*)bp;
        ap += 16; bp += 16;

        __syncthreads();
        As[lk + 0][lr] = aa.x; As[lk + 1][lr] = aa.y; As[lk + 2][lr] = aa.z; As[lk + 3][lr] = aa.w;
        Bs[lk + 0][lr] = bb.x; Bs[lk + 1][lr] = bb.y; Bs[lk + 2][lr] = bb.z; Bs[lk + 3][lr] = bb.w;
        __syncthreads();

#pragma unroll
        for (int kk = 0; kk < 16; kk++) {
            float4 a4 = *(const float4*)&As[kk][ty * 4];
            float4 b4 = *(const float4*)&Bs[kk][tx * 4];
            float aa2[4] = {a4.x, a4.y, a4.z, a4.w};
            float bb2[4] = {b4.x, b4.y, b4.z, b4.w};
#pragma unroll
            for (int i2 = 0; i2 < 4; i2++)
#pragma unroll
                for (int j = 0; j < 4; j++)
                    c[i2][j] += aa2[i2] * bb2[j];
        }
    }

#pragma unroll
    for (int i2 = 0; i2 < 4; i2++) {
        int m = m0 + ty * 4 + i2;
        if (m < cnt) {
            int a = g_perm[base + m];
            float4 o = make_float4(c[i2][0], c[i2][1], c[i2][2], c[i2][3]);
            *(float4*)&g_y[(size_t)a * H_ + (size_t)(h0 + tx * 4)] = o;
        }
    }
}

// ---------------- combine: out[t,h] = w0*y[2t,h] + w1*y[2t+1,h] ----------------
__global__ void combine_kernel(float* __restrict__ out) {
    int idx = blockIdx.x * blockDim.x + threadIdx.x;   // over T_*H_/4 float4s
    int t  = idx >> 9;        // H_/4 = 512 float4s per token
    int h4 = idx & 511;
    float w0 = g_aw[2 * t];
    float w1 = g_aw[2 * t + 1];
    float4 y0 = *(const float4*)&g_y[(size_t)(2 * t)     * H_ + (size_t)h4 * 4];
    float4 y1 = *(const float4*)&g_y[(size_t)(2 * t + 1) * H_ + (size_t)h4 * 4];
    float4 o;
    o.x = w0 * y0.x + w1 * y1.x;
    o.y = w0 * y0.y + w1 * y1.y;
    o.z = w0 * y0.z + w1 * y1.z;
    o.w = w0 * y0.w + w1 * y1.w;
    *(float4*)&out[(size_t)t * H_ + (size_t)h4 * 4] = o;
}

extern "C" void kernel_launch(void* const* d_in, const int* in_sizes, int n_in,
                              void* d_out, int out_size) {
    const float* x   = (const float*)d_in[0];   // [512, 2048]
    const float* rl  = (const float*)d_in[1];   // [512, 8]
    const float* w13 = (const float*)d_in[2];   // [8, 11264, 2048]
    const float* w2  = (const float*)d_in[3];   // [8, 2048, 5632]
    float* out = (float*)d_out;                 // [512, 2048]
    (void)in_sizes; (void)n_in; (void)out_size; // top_k fixed at 2

    route_kernel<<<1, T_>>>(rl);
    // grid.y = 8 covers the worst case of one expert receiving all 512 tokens
    gemm1_kernel<<<dim3(I_ / 64, 8, E_), 256>>>(x, w13);
    gemm2_kernel<<<dim3(H_ / 64, 8, E_), 256>>>(w2);
    combine_kernel<<<(T_ * H_ / 4) / 512, 512>>>(out);
}

// round 4
// speedup vs baseline: 2.0580x; 2.0580x over previous
#include <cuda_runtime.h>
#include <cstdint>
#include <math.h>

// Problem constants
#define T_ 512
#define E_ 8
#define H_ 2048
#define I_ 5632
#define A_ (2 * T_)   // 1024 token-expert assignments (top_k = 2)

// ---------------- scratch (device globals; no allocation allowed) ----------------
__device__ float g_gu[(size_t)A_ * 2 * I_];  // raw gate_up, perm order [1024, 11264]
__device__ float g_act[(size_t)A_ * I_];     // SwiGLU activations, perm order [1024, 5632]
__device__ float g_y[(size_t)A_ * H_];       // down-proj outputs, assignment order [1024, 2048]
__device__ int   g_perm[A_];                 // assignment ids grouped by expert
__device__ int   g_offs[E_ + 1];             // expert segment offsets into g_perm
__device__ float g_aw[A_];                   // renormalized top-2 weights, a = 2*t + k

// ---------------- helpers ----------------
__device__ __forceinline__ uint32_t f2t(float f) {   // fp32 -> tf32 (round to nearest)
    uint32_t r;
    asm("cvt.rna.tf32.f32 %0, %1;" : "=r"(r) : "f"(f));
    return r;
}
__device__ __forceinline__ uint4 cvt4(float4 v) {
    uint4 o; o.x = f2t(v.x); o.y = f2t(v.y); o.z = f2t(v.z); o.w = f2t(v.w); return o;
}
__device__ __forceinline__ void mma_tf32(float* d, const uint32_t* a, const uint32_t* b) {
    asm volatile(
        "mma.sync.aligned.m16n8k8.row.col.f32.tf32.tf32.f32 "
        "{%0,%1,%2,%3}, {%4,%5,%6,%7}, {%8,%9}, {%0,%1,%2,%3};"
        : "+f"(d[0]), "+f"(d[1]), "+f"(d[2]), "+f"(d[3])
        : "r"(a[0]), "r"(a[1]), "r"(a[2]), "r"(a[3]), "r"(b[0]), "r"(b[1]));
}

// ---------------- routing ----------------
__global__ void route_kernel(const float* __restrict__ logits) {
    __shared__ unsigned char s_e[A_];
    __shared__ int s_cnt[E_];
    __shared__ int s_off[E_ + 1];

    int t = threadIdx.x;
    if (t < E_) s_cnt[t] = 0;
    __syncthreads();

    float l[E_];
#pragma unroll
    for (int e = 0; e < E_; e++) l[e] = logits[t * E_ + e];

    int e0 = 0;
#pragma unroll
    for (int e = 1; e < E_; e++) if (l[e] > l[e0]) e0 = e;
    int e1 = (e0 == 0) ? 1 : 0;
#pragma unroll
    for (int e = 0; e < E_; e++) if (e != e0 && l[e] > l[e1]) e1 = e;

    float p1 = __expf(l[e1] - l[e0]);
    float inv = 1.0f / (1.0f + p1);
    g_aw[2 * t + 0] = inv;
    g_aw[2 * t + 1] = p1 * inv;

    s_e[2 * t + 0] = (unsigned char)e0;
    s_e[2 * t + 1] = (unsigned char)e1;
    atomicAdd(&s_cnt[e0], 1);
    atomicAdd(&s_cnt[e1], 1);
    __syncthreads();

    if (t == 0) {
        int acc = 0;
        for (int e = 0; e < E_; e++) { s_off[e] = acc; acc += s_cnt[e]; }
        s_off[E_] = acc;
        for (int e = 0; e <= E_; e++) g_offs[e] = s_off[e];
    }
    __syncthreads();

#pragma unroll
    for (int k = 0; k < 2; k++) {
        int a = 2 * t + k;
        int e = s_e[a];
        int rank = 0;
        for (int b = 0; b < a; b++) rank += (s_e[b] == e) ? 1 : 0;
        g_perm[s_off[e] + rank] = a;
    }
}

// =================================================================================
// Tiled tf32 mma.sync GEMM.  C[128,128] per CTA, 8 warps (2M x 4N, 64x32 each),
// K staged 32/iter, double-buffered smem with register prefetch, XOR chunk swizzle.
//   IS_G1: A = x gathered via perm>>1 (K=2048), B = w13 rows, Out = g_gu (perm order)
//  !IS_G1: A = g_act rows (K=5632),              B = w2 rows,  Out = g_y (scatter via perm)
// Scratch operands are resolved IN-KERNEL from device globals (no null pointers).
// Dynamic smem: A0|B0|A1|B1 (4 x 16KB) + s_row (512B) = 66048 B.
// =================================================================================
#define GM_SMEM (4 * 16384 + 512)

// swizzled byte offset inside a 128x32-float tile: row-major 128B rows, 16B chunk XOR
__device__ __forceinline__ uint32_t tswz(int row, int k) {
    return (uint32_t)(row * 128 + (((k >> 2) ^ (row & 7)) << 4) + ((k & 3) << 2));
}

template<bool IS_G1>
__global__ __launch_bounds__(256, 1)
void moe_gemm(const float* __restrict__ x, const float* __restrict__ Bsrc)
{
    constexpr int KT = IS_G1 ? H_ : I_;        // K depth (A and B row stride)
    constexpr int NS = KT / 32;                // stages
    constexpr int NOUT = IS_G1 ? 2 * I_ : H_;  // B rows per expert == out row stride

    const float* Asrc = IS_G1 ? x : (const float*)g_act;
    float* Out = IS_G1 ? g_gu : g_y;

    extern __shared__ char sm[];
    char* smA[2] = { sm,          sm + 32768 };
    char* smB[2] = { sm + 16384,  sm + 49152 };
    int* s_row = (int*)(sm + 65536);

    const int e = blockIdx.z;
    const int base = g_offs[e];
    const int cnt = g_offs[e + 1] - base;
    const int m0 = blockIdx.y * 128;
    if (m0 >= cnt) return;
    const int n0 = blockIdx.x * 128;

    const int tid = threadIdx.x;
    const int wid = tid >> 5, lid = tid & 31;
    const int gid = lid >> 2, tig = lid & 3;
    const int wm = wid & 1, wn = wid >> 1;

    if (tid < 128) {
        int m = m0 + tid;
        int mm = (m < cnt) ? m : 0;
        s_row[tid] = IS_G1 ? (g_perm[base + mm] >> 1) : (base + mm);
    }
    __syncthreads();

    // loader: 4 float4 per tile per thread; lanes 0-7 share a row (conflict-free phases)
    const float* ap[4]; const float* bp[4]; uint32_t so[4];
#pragma unroll
    for (int t = 0; t < 4; t++) {
        int idx = t * 256 + tid;
        int row = idx >> 3, q = idx & 7;
        so[t] = (uint32_t)(row * 128 + ((q ^ (row & 7)) << 4));
        ap[t] = Asrc + (size_t)s_row[row] * KT + q * 4;
        bp[t] = Bsrc + ((size_t)e * NOUT + (size_t)(n0 + row)) * KT + q * 4;
    }

    float4 ra[4], rb[4];
    auto LDG = [&]() {
#pragma unroll
        for (int t = 0; t < 4; t++) {
            ra[t] = *(const float4*)ap[t];
            rb[t] = *(const float4*)bp[t];
            ap[t] += 32; bp[t] += 32;
        }
    };
    auto STS = [&](int b) {
#pragma unroll
        for (int t = 0; t < 4; t++) {
            *(uint4*)(smA[b] + so[t]) = cvt4(ra[t]);
            *(uint4*)(smB[b] + so[t]) = cvt4(rb[t]);
        }
    };

    float c[4][4][4] = {};

    // prologue
    LDG(); STS(0); LDG();
    __syncthreads();

    for (int s = 0; s < NS; s++) {
        const int cur = s & 1;
        if (s + 1 < NS) STS((s + 1) & 1);
        if (s + 2 < NS) LDG();

        const char* A = smA[cur];
        const char* B = smB[cur];
#pragma unroll
        for (int kt = 0; kt < 4; kt++) {
            uint32_t af[4][4], bf[4][2];
#pragma unroll
            for (int mt = 0; mt < 4; mt++) {
                int rbase = wm * 64 + mt * 16 + gid;
#pragma unroll
                for (int cc = 0; cc < 2; cc++) {
                    int k = kt * 8 + tig + cc * 4;
                    af[mt][0 + 2 * cc] = *(const uint32_t*)(A + tswz(rbase,     k));
                    af[mt][1 + 2 * cc] = *(const uint32_t*)(A + tswz(rbase + 8, k));
                }
            }
#pragma unroll
            for (int nt = 0; nt < 4; nt++) {
                int n = wn * 32 + nt * 8 + gid;
                bf[nt][0] = *(const uint32_t*)(B + tswz(n, kt * 8 + tig));
                bf[nt][1] = *(const uint32_t*)(B + tswz(n, kt * 8 + tig + 4));
            }
#pragma unroll
            for (int mt = 0; mt < 4; mt++)
#pragma unroll
                for (int nt = 0; nt < 4; nt++)
                    mma_tf32(c[mt][nt], af[mt], bf[nt]);
        }
        __syncthreads();
    }

    // epilogue: fp32 stores with row guard (no cross-expert corruption)
#pragma unroll
    for (int mt = 0; mt < 4; mt++) {
#pragma unroll
        for (int rr = 0; rr < 2; rr++) {
            int m = m0 + wm * 64 + mt * 16 + gid + rr * 8;
            if (m < cnt) {
                int orow = IS_G1 ? (base + m) : g_perm[base + m];
                float* op = Out + (size_t)orow * NOUT + (size_t)(n0 + wn * 32) + 2 * tig;
#pragma unroll
                for (int nt = 0; nt < 4; nt++) {
                    float2 v = make_float2(c[mt][nt][2 * rr], c[mt][nt][2 * rr + 1]);
                    *(float2*)(op + nt * 8) = v;
                }
            }
        }
    }
}

// ---------------- SwiGLU elementwise: act = silu(gate) * up ----------------
__global__ void swiglu_kernel() {
    int idx = blockIdx.x * blockDim.x + threadIdx.x;   // over A_*I_/4 float4s
    int r  = idx / (I_ / 4);
    int c4 = idx % (I_ / 4);
    const float* gp = g_gu + (size_t)r * (2 * I_) + (size_t)c4 * 4;
    float4 g = *(const float4*)gp;
    float4 u = *(const float4*)(gp + I_);
    float4 o;
    o.x = (g.x / (1.0f + __expf(-g.x))) * u.x;
    o.y = (g.y / (1.0f + __expf(-g.y))) * u.y;
    o.z = (g.z / (1.0f + __expf(-g.z))) * u.z;
    o.w = (g.w / (1.0f + __expf(-g.w))) * u.w;
    *(float4*)&g_act[(size_t)r * I_ + (size_t)c4 * 4] = o;
}

// ---------------- combine: out[t,h] = w0*y[2t,h] + w1*y[2t+1,h] ----------------
__global__ void combine_kernel(float* __restrict__ out) {
    int idx = blockIdx.x * blockDim.x + threadIdx.x;
    int t  = idx >> 9;
    int h4 = idx & 511;
    float w0 = g_aw[2 * t];
    float w1 = g_aw[2 * t + 1];
    float4 y0 = *(const float4*)&g_y[(size_t)(2 * t)     * H_ + (size_t)h4 * 4];
    float4 y1 = *(const float4*)&g_y[(size_t)(2 * t + 1) * H_ + (size_t)h4 * 4];
    float4 o;
    o.x = w0 * y0.x + w1 * y1.x;
    o.y = w0 * y0.y + w1 * y1.y;
    o.z = w0 * y0.z + w1 * y1.z;
    o.w = w0 * y0.w + w1 * y1.w;
    *(float4*)&out[(size_t)t * H_ + (size_t)h4 * 4] = o;
}

extern "C" void kernel_launch(void* const* d_in, const int* in_sizes, int n_in,
                              void* d_out, int out_size) {
    const float* x   = (const float*)d_in[0];   // [512, 2048]
    const float* rl  = (const float*)d_in[1];   // [512, 8]
    const float* w13 = (const float*)d_in[2];   // [8, 11264, 2048]
    const float* w2  = (const float*)d_in[3];   // [8, 2048, 5632]
    float* out = (float*)d_out;                 // [512, 2048]
    (void)in_sizes; (void)n_in; (void)out_size;

    cudaFuncSetAttribute(moe_gemm<true>,  cudaFuncAttributeMaxDynamicSharedMemorySize, GM_SMEM);
    cudaFuncSetAttribute(moe_gemm<false>, cudaFuncAttributeMaxDynamicSharedMemorySize, GM_SMEM);

    route_kernel<<<1, T_>>>(rl);
    // GEMM1: x @ w13^T -> g_gu (raw). grid.y = 4 covers worst case (512 tokens on one expert)
    moe_gemm<true><<<dim3(2 * I_ / 128, 4, E_), 256, GM_SMEM>>>(x, w13);
    swiglu_kernel<<<(A_ * I_ / 4) / 256, 256>>>();
    // GEMM2: act @ w2^T -> g_y (scatter to assignment order)
    moe_gemm<false><<<dim3(H_ / 128, 4, E_), 256, GM_SMEM>>>(x, w2);
    combine_kernel<<<(T_ * H_ / 4) / 512, 512>>>(out);
}

// round 5
// speedup vs baseline: 3.1918x; 1.5510x over previous
#include <cuda_runtime.h>
#include <cstdint>
#include <math.h>

// Problem constants
#define T_ 512
#define E_ 8
#define H_ 2048
#define I_ 5632
#define A_ (2 * T_)   // 1024 token-expert assignments (top_k = 2)

// ---------------- scratch (device globals; no allocation allowed) ----------------
__device__ float g_gu[(size_t)A_ * 2 * I_];  // raw gate_up, perm order [1024, 11264]
__device__ float g_act[(size_t)A_ * I_];     // SwiGLU activations, perm order [1024, 5632]
__device__ float g_y[(size_t)A_ * H_];       // down-proj outputs, assignment order [1024, 2048]
__device__ int   g_perm[A_];                 // assignment ids grouped by expert
__device__ int   g_offs[E_ + 1];             // expert segment offsets into g_perm
__device__ float g_aw[A_];                   // renormalized top-2 weights, a = 2*t + k

// ---------------- helpers ----------------
__device__ __forceinline__ uint32_t f2t(float f) {   // fp32 -> tf32 (round to nearest)
    uint32_t r;
    asm("cvt.rna.tf32.f32 %0, %1;" : "=r"(r) : "f"(f));
    return r;
}
__device__ __forceinline__ void mma_tf32(float* d, const uint32_t* a, const uint32_t* b) {
    asm volatile(
        "mma.sync.aligned.m16n8k8.row.col.f32.tf32.tf32.f32 "
        "{%0,%1,%2,%3}, {%4,%5,%6,%7}, {%8,%9}, {%0,%1,%2,%3};"
        : "+f"(d[0]), "+f"(d[1]), "+f"(d[2]), "+f"(d[3])
        : "r"(a[0]), "r"(a[1]), "r"(a[2]), "r"(a[3]), "r"(b[0]), "r"(b[1]));
}
__device__ __forceinline__ uint32_t smem_u32(const void* p) {
    return (uint32_t)__cvta_generic_to_shared(p);
}
#define CP_ASYNC16(dst, src) \
    asm volatile("cp.async.cg.shared.global [%0], [%1], 16;" :: "r"(dst), "l"(src))
#define CP_COMMIT() asm volatile("cp.async.commit_group;" ::: "memory")
#define CP_WAIT(n)  asm volatile("cp.async.wait_group %0;" :: "n"(n) : "memory")

// ---------------- routing ----------------
__global__ void route_kernel(const float* __restrict__ logits) {
    __shared__ unsigned char s_e[A_];
    __shared__ int s_cnt[E_];
    __shared__ int s_off[E_ + 1];

    int t = threadIdx.x;
    if (t < E_) s_cnt[t] = 0;
    __syncthreads();

    float l[E_];
#pragma unroll
    for (int e = 0; e < E_; e++) l[e] = logits[t * E_ + e];

    int e0 = 0;
#pragma unroll
    for (int e = 1; e < E_; e++) if (l[e] > l[e0]) e0 = e;
    int e1 = (e0 == 0) ? 1 : 0;
#pragma unroll
    for (int e = 0; e < E_; e++) if (e != e0 && l[e] > l[e1]) e1 = e;

    float p1 = __expf(l[e1] - l[e0]);
    float inv = 1.0f / (1.0f + p1);
    g_aw[2 * t + 0] = inv;
    g_aw[2 * t + 1] = p1 * inv;

    s_e[2 * t + 0] = (unsigned char)e0;
    s_e[2 * t + 1] = (unsigned char)e1;
    atomicAdd(&s_cnt[e0], 1);
    atomicAdd(&s_cnt[e1], 1);
    __syncthreads();

    if (t == 0) {
        int acc = 0;
        for (int e = 0; e < E_; e++) { s_off[e] = acc; acc += s_cnt[e]; }
        s_off[E_] = acc;
        for (int e = 0; e <= E_; e++) g_offs[e] = s_off[e];
    }
    __syncthreads();

#pragma unroll
    for (int k = 0; k < 2; k++) {
        int a = 2 * t + k;
        int e = s_e[a];
        int rank = 0;
        for (int b = 0; b < a; b++) rank += (s_e[b] == e) ? 1 : 0;
        g_perm[s_off[e] + rank] = a;
    }
}

// =================================================================================
// Tiled tf32 mma.sync GEMM with cp.async 4-stage pipeline.
// C[128,128] per CTA, 8 warps (2M x 4N, 64x32 each), K=32 per stage.
//   IS_G1: A = x gathered via perm>>1 (K=2048), B = w13 rows, Out = g_gu (perm order)
//  !IS_G1: A = g_act rows (K=5632),              B = w2 rows,  Out = g_y (scatter via perm)
// smem: 4 stages x (A 16KB | B 16KB) = 128KB, + s_row 512B.
// tf32 conversion (cvt.rna) happens at fragment-read time; smem holds raw fp32.
// =================================================================================
#define STAGES 4
#define STG_BYTES 32768
#define GM_SMEM (STAGES * STG_BYTES + 512)

// swizzled byte offset inside a 128x32-float tile: 128B rows, 16B chunk XOR
__device__ __forceinline__ uint32_t tswz(int row, int k) {
    return (uint32_t)(row * 128 + (((k >> 2) ^ (row & 7)) << 4) + ((k & 3) << 2));
}

template<bool IS_G1>
__global__ __launch_bounds__(256, 1)
void moe_gemm(const float* __restrict__ x, const float* __restrict__ Bsrc)
{
    constexpr int KT = IS_G1 ? H_ : I_;        // K depth (row stride of A and B)
    constexpr int NS = KT / 32;                // number of K stages
    constexpr int NOUT = IS_G1 ? 2 * I_ : H_;  // B rows per expert == out row stride

    const float* Asrc = IS_G1 ? x : (const float*)g_act;
    float* Out = IS_G1 ? g_gu : g_y;

    extern __shared__ char sm[];
    int* s_row = (int*)(sm + STAGES * STG_BYTES);

    const int e = blockIdx.z;
    const int base = g_offs[e];
    const int cnt = g_offs[e + 1] - base;
    const int m0 = blockIdx.y * 128;
    if (m0 >= cnt) return;
    const int n0 = blockIdx.x * 128;

    const int tid = threadIdx.x;
    const int wid = tid >> 5, lid = tid & 31;
    const int gid = lid >> 2, tig = lid & 3;
    const int wm = wid & 1, wn = wid >> 1;

    if (tid < 128) {
        int m = m0 + tid;
        int mm = (m < cnt) ? m : 0;
        s_row[tid] = IS_G1 ? (g_perm[base + mm] >> 1) : (base + mm);
    }
    __syncthreads();

    // per-thread copy slots: 4 x 16B for A, 4 x 16B for B per stage
    const float* ap[4]; const float* bp[4]; uint32_t so[4];
#pragma unroll
    for (int t = 0; t < 4; t++) {
        int idx = t * 256 + tid;
        int row = idx >> 3, q = idx & 7;
        so[t] = (uint32_t)(row * 128 + ((q ^ (row & 7)) << 4));
        ap[t] = Asrc + (size_t)s_row[row] * KT + q * 4;
        bp[t] = Bsrc + ((size_t)e * NOUT + (size_t)(n0 + row)) * KT + q * 4;
    }

    const uint32_t smbase = smem_u32(sm);
    auto issue = [&](int stage) {
        uint32_t ab = smbase + (uint32_t)(stage % STAGES) * STG_BYTES;
        uint32_t bb = ab + 16384;
#pragma unroll
        for (int t = 0; t < 4; t++) {
            CP_ASYNC16(ab + so[t], ap[t]);
            CP_ASYNC16(bb + so[t], bp[t]);
            ap[t] += 32; bp[t] += 32;
        }
    };

    // prologue: stages 0..STAGES-2 in flight
#pragma unroll
    for (int p = 0; p < STAGES - 1; p++) { issue(p); CP_COMMIT(); }

    float c[4][4][4] = {};

    for (int s = 0; s < NS; s++) {
        CP_WAIT(STAGES - 2);      // stage s resident
        __syncthreads();          // all warps see it; all warps done with stage s-1

        if (s + STAGES - 1 < NS) issue(s + STAGES - 1);   // refill just-freed buffer
        CP_COMMIT();              // commit (possibly empty) to keep group count uniform

        const char* A = sm + (s % STAGES) * STG_BYTES;
        const char* B = A + 16384;
#pragma unroll
        for (int kt = 0; kt < 4; kt++) {
            uint32_t af[4][4], bf[4][2];
#pragma unroll
            for (int mt = 0; mt < 4; mt++) {
                int rbase = wm * 64 + mt * 16 + gid;
#pragma unroll
                for (int cc = 0; cc < 2; cc++) {
                    int k = kt * 8 + tig + cc * 4;
                    af[mt][0 + 2 * cc] = f2t(*(const float*)(A + tswz(rbase,     k)));
                    af[mt][1 + 2 * cc] = f2t(*(const float*)(A + tswz(rbase + 8, k)));
                }
            }
#pragma unroll
            for (int nt = 0; nt < 4; nt++) {
                int n = wn * 32 + nt * 8 + gid;
                bf[nt][0] = f2t(*(const float*)(B + tswz(n, kt * 8 + tig)));
                bf[nt][1] = f2t(*(const float*)(B + tswz(n, kt * 8 + tig + 4)));
            }
#pragma unroll
            for (int mt = 0; mt < 4; mt++)
#pragma unroll
                for (int nt = 0; nt < 4; nt++)
                    mma_tf32(c[mt][nt], af[mt], bf[nt]);
        }
        __syncthreads();          // finish reads before this buffer is refilled next iter
    }

    // epilogue: fp32 stores with row guard (no cross-expert corruption)
#pragma unroll
    for (int mt = 0; mt < 4; mt++) {
#pragma unroll
        for (int rr = 0; rr < 2; rr++) {
            int m = m0 + wm * 64 + mt * 16 + gid + rr * 8;
            if (m < cnt) {
                int orow = IS_G1 ? (base + m) : g_perm[base + m];
                float* op = Out + (size_t)orow * NOUT + (size_t)(n0 + wn * 32) + 2 * tig;
#pragma unroll
                for (int nt = 0; nt < 4; nt++) {
                    float2 v = make_float2(c[mt][nt][2 * rr], c[mt][nt][2 * rr + 1]);
                    *(float2*)(op + nt * 8) = v;
                }
            }
        }
    }
}

// ---------------- SwiGLU elementwise: act = silu(gate) * up ----------------
__global__ void swiglu_kernel() {
    int idx = blockIdx.x * blockDim.x + threadIdx.x;   // over A_*I_/4 float4s
    int r  = idx / (I_ / 4);
    int c4 = idx % (I_ / 4);
    const float* gp = g_gu + (size_t)r * (2 * I_) + (size_t)c4 * 4;
    float4 g = *(const float4*)gp;
    float4 u = *(const float4*)(gp + I_);
    float4 o;
    o.x = (g.x / (1.0f + __expf(-g.x))) * u.x;
    o.y = (g.y / (1.0f + __expf(-g.y))) * u.y;
    o.z = (g.z / (1.0f + __expf(-g.z))) * u.z;
    o.w = (g.w / (1.0f + __expf(-g.w))) * u.w;
    *(float4*)&g_act[(size_t)r * I_ + (size_t)c4 * 4] = o;
}

// ---------------- combine: out[t,h] = w0*y[2t,h] + w1*y[2t+1,h] ----------------
__global__ void combine_kernel(float* __restrict__ out) {
    int idx = blockIdx.x * blockDim.x + threadIdx.x;
    int t  = idx >> 9;
    int h4 = idx & 511;
    float w0 = g_aw[2 * t];
    float w1 = g_aw[2 * t + 1];
    float4 y0 = *(const float4*)&g_y[(size_t)(2 * t)     * H_ + (size_t)h4 * 4];
    float4 y1 = *(const float4*)&g_y[(size_t)(2 * t + 1) * H_ + (size_t)h4 * 4];
    float4 o;
    o.x = w0 * y0.x + w1 * y1.x;
    o.y = w0 * y0.y + w1 * y1.y;
    o.z = w0 * y0.z + w1 * y1.z;
    o.w = w0 * y0.w + w1 * y1.w;
    *(float4*)&out[(size_t)t * H_ + (size_t)h4 * 4] = o;
}

extern "C" void kernel_launch(void* const* d_in, const int* in_sizes, int n_in,
                              void* d_out, int out_size) {
    const float* x   = (const float*)d_in[0];   // [512, 2048]
    const float* rl  = (const float*)d_in[1];   // [512, 8]
    const float* w13 = (const float*)d_in[2];   // [8, 11264, 2048]
    const float* w2  = (const float*)d_in[3];   // [8, 2048, 5632]
    float* out = (float*)d_out;                 // [512, 2048]
    (void)in_sizes; (void)n_in; (void)out_size;

    cudaFuncSetAttribute(moe_gemm<true>,  cudaFuncAttributeMaxDynamicSharedMemorySize, GM_SMEM);
    cudaFuncSetAttribute(moe_gemm<false>, cudaFuncAttributeMaxDynamicSharedMemorySize, GM_SMEM);

    route_kernel<<<1, T_>>>(rl);
    // GEMM1: x @ w13^T -> g_gu (raw). grid.y = 4 covers worst case (512 tokens on one expert)
    moe_gemm<true><<<dim3(2 * I_ / 128, 4, E_), 256, GM_SMEM>>>(x, w13);
    swiglu_kernel<<<(A_ * I_ / 4) / 256, 256>>>();
    // GEMM2: act @ w2^T -> g_y (scatter to assignment order)
    moe_gemm<false><<<dim3(H_ / 128, 4, E_), 256, GM_SMEM>>>(x, w2);
    combine_kernel<<<(T_ * H_ / 4) / 512, 512>>>(out);
}

// round 6
// speedup vs baseline: 3.2712x; 1.0249x over previous
#include <cuda_runtime.h>
#include <cstdint>
#include <math.h>

// Problem constants
#define T_ 512
#define E_ 8
#define H_ 2048
#define I_ 5632
#define A_ (2 * T_)   // 1024 token-expert assignments (top_k = 2)

// ---------------- scratch (device globals; no allocation allowed) ----------------
__device__ float g_act[(size_t)A_ * I_];     // SwiGLU activations, perm order [1024, 5632]
__device__ float g_y[(size_t)A_ * H_];       // down-proj outputs, assignment order [1024, 2048]
__device__ int   g_perm[A_];                 // assignment ids grouped by expert
__device__ int   g_offs[E_ + 1];             // expert segment offsets into g_perm
__device__ float g_aw[A_];                   // renormalized top-2 weights, a = 2*t + k

// ---------------- helpers ----------------
__device__ __forceinline__ uint32_t f2t(float f) {   // fp32 -> tf32 (round to nearest)
    uint32_t r;
    asm("cvt.rna.tf32.f32 %0, %1;" : "=r"(r) : "f"(f));
    return r;
}
__device__ __forceinline__ void mma_tf32(float* d, const uint32_t* a, const uint32_t* b) {
    asm volatile(
        "mma.sync.aligned.m16n8k8.row.col.f32.tf32.tf32.f32 "
        "{%0,%1,%2,%3}, {%4,%5,%6,%7}, {%8,%9}, {%0,%1,%2,%3};"
        : "+f"(d[0]), "+f"(d[1]), "+f"(d[2]), "+f"(d[3])
        : "r"(a[0]), "r"(a[1]), "r"(a[2]), "r"(a[3]), "r"(b[0]), "r"(b[1]));
}
__device__ __forceinline__ uint32_t smem_u32(const void* p) {
    return (uint32_t)__cvta_generic_to_shared(p);
}
#define CP_ASYNC16(dst, src) \
    asm volatile("cp.async.cg.shared.global [%0], [%1], 16;" :: "r"(dst), "l"(src))
#define CP_COMMIT() asm volatile("cp.async.commit_group;" ::: "memory")
#define CP_WAIT(n)  asm volatile("cp.async.wait_group %0;" :: "n"(n) : "memory")

// swizzled byte offset inside a (rows x 32-float) tile: 128B rows, 16B chunk XOR
__device__ __forceinline__ uint32_t tswz(int row, int k) {
    return (uint32_t)(row * 128 + (((k >> 2) ^ (row & 7)) << 4) + ((k & 3) << 2));
}

// ---------------- routing ----------------
__global__ void route_kernel(const float* __restrict__ logits) {
    __shared__ unsigned char s_e[A_];
    __shared__ int s_cnt[E_];
    __shared__ int s_off[E_ + 1];

    int t = threadIdx.x;
    if (t < E_) s_cnt[t] = 0;
    __syncthreads();

    float l[E_];
#pragma unroll
    for (int e = 0; e < E_; e++) l[e] = logits[t * E_ + e];

    int e0 = 0;
#pragma unroll
    for (int e = 1; e < E_; e++) if (l[e] > l[e0]) e0 = e;
    int e1 = (e0 == 0) ? 1 : 0;
#pragma unroll
    for (int e = 0; e < E_; e++) if (e != e0 && l[e] > l[e1]) e1 = e;

    float p1 = __expf(l[e1] - l[e0]);
    float inv = 1.0f / (1.0f + p1);
    g_aw[2 * t + 0] = inv;
    g_aw[2 * t + 1] = p1 * inv;

    s_e[2 * t + 0] = (unsigned char)e0;
    s_e[2 * t + 1] = (unsigned char)e1;
    atomicAdd(&s_cnt[e0], 1);
    atomicAdd(&s_cnt[e1], 1);
    __syncthreads();

    if (t == 0) {
        int acc = 0;
        for (int e = 0; e < E_; e++) { s_off[e] = acc; acc += s_cnt[e]; }
        s_off[E_] = acc;
        for (int e = 0; e <= E_; e++) g_offs[e] = s_off[e];
    }
    __syncthreads();

#pragma unroll
    for (int k = 0; k < 2; k++) {
        int a = 2 * t + k;
        int e = s_e[a];
        int rank = 0;
        for (int b = 0; b < a; b++) rank += (s_e[b] == e) ? 1 : 0;
        g_perm[s_off[e] + rank] = a;
    }
}

#define STAGES 3
#define STG_BYTES 32768
#define GM_SMEM (STAGES * STG_BYTES + 512)

// =================================================================================
// GEMM1 fused: act[m, i0..i0+64) = silu(x@Wg^T) * (x@Wu^T) per expert.
// CTA tile: M=128, N=64 (gate) + N=64 (up). 8 warps = 4M x 2N, 32x32 each (x2 g/u).
// K=32 per stage; smem per stage: A 16KB | Bg 8KB | Bu 8KB. 3 stages = 96KB.
// tf32 cvt at fragment read; SwiGLU in epilogue -> writes g_act directly.
// =================================================================================
__global__ __launch_bounds__(256, 2)
void gemm1_fused(const float* __restrict__ x, const float* __restrict__ w13)
{
    constexpr int KT = H_;
    constexpr int NS = KT / 32;   // 64 stages

    extern __shared__ char sm[];
    int* s_row = (int*)(sm + STAGES * STG_BYTES);

    const int e = blockIdx.z;
    const int base = g_offs[e];
    const int cnt = g_offs[e + 1] - base;
    const int m0 = blockIdx.y * 128;
    if (m0 >= cnt) return;
    const int i0 = blockIdx.x * 64;

    const int tid = threadIdx.x;
    const int wid = tid >> 5, lid = tid & 31;
    const int gid = lid >> 2, tig = lid & 3;
    const int wm = wid >> 1, wn = wid & 1;   // 4M x 2N

    if (tid < 128) {
        int m = m0 + tid;
        int mm = (m < cnt) ? m : 0;
        s_row[tid] = g_perm[base + mm] >> 1;
    }
    __syncthreads();

    // copy slots: A 4 chunks/thread, Bg 2, Bu 2 (16B each)
    const float* ap[4]; uint32_t soA[4];
    const float* gp[2]; const float* up[2]; uint32_t soB[2];
#pragma unroll
    for (int t = 0; t < 4; t++) {
        int idx = t * 256 + tid;
        int row = idx >> 3, q = idx & 7;
        soA[t] = (uint32_t)(row * 128 + ((q ^ (row & 7)) << 4));
        ap[t] = x + (size_t)s_row[row] * KT + q * 4;
    }
#pragma unroll
    for (int t = 0; t < 2; t++) {
        int idx = t * 256 + tid;
        int row = idx >> 3, q = idx & 7;   // row 0..63
        soB[t] = (uint32_t)(row * 128 + ((q ^ (row & 7)) << 4));
        gp[t] = w13 + ((size_t)e * (2 * I_) + (size_t)(i0 + row)) * KT + q * 4;
        up[t] = w13 + ((size_t)e * (2 * I_) + (size_t)(I_ + i0 + row)) * KT + q * 4;
    }

    const uint32_t smbase = smem_u32(sm);
    auto issue = [&](int stage) {
        uint32_t ab = smbase + (uint32_t)(stage % STAGES) * STG_BYTES;
        uint32_t gb = ab + 16384;
        uint32_t ub = gb + 8192;
#pragma unroll
        for (int t = 0; t < 4; t++) { CP_ASYNC16(ab + soA[t], ap[t]); ap[t] += 32; }
#pragma unroll
        for (int t = 0; t < 2; t++) {
            CP_ASYNC16(gb + soB[t], gp[t]); gp[t] += 32;
            CP_ASYNC16(ub + soB[t], up[t]); up[t] += 32;
        }
    };

#pragma unroll
    for (int p = 0; p < STAGES - 1; p++) { issue(p); CP_COMMIT(); }

    float cg[2][4][4] = {}, cu[2][4][4] = {};

    for (int s = 0; s < NS; s++) {
        CP_WAIT(STAGES - 2);
        __syncthreads();
        if (s + STAGES - 1 < NS) issue(s + STAGES - 1);
        CP_COMMIT();

        const char* A  = sm + (s % STAGES) * STG_BYTES;
        const char* Bg = A + 16384;
        const char* Bu = Bg + 8192;
#pragma unroll
        for (int kt = 0; kt < 4; kt++) {
            uint32_t af[2][4], bg[4][2], bu[4][2];
#pragma unroll
            for (int mt = 0; mt < 2; mt++) {
                int rbase = wm * 32 + mt * 16 + gid;
#pragma unroll
                for (int cc = 0; cc < 2; cc++) {
                    int k = kt * 8 + tig + cc * 4;
                    af[mt][0 + 2 * cc] = f2t(*(const float*)(A + tswz(rbase,     k)));
                    af[mt][1 + 2 * cc] = f2t(*(const float*)(A + tswz(rbase + 8, k)));
                }
            }
#pragma unroll
            for (int nt = 0; nt < 4; nt++) {
                int n = wn * 32 + nt * 8 + gid;
                bg[nt][0] = f2t(*(const float*)(Bg + tswz(n, kt * 8 + tig)));
                bg[nt][1] = f2t(*(const float*)(Bg + tswz(n, kt * 8 + tig + 4)));
                bu[nt][0] = f2t(*(const float*)(Bu + tswz(n, kt * 8 + tig)));
                bu[nt][1] = f2t(*(const float*)(Bu + tswz(n, kt * 8 + tig + 4)));
            }
#pragma unroll
            for (int mt = 0; mt < 2; mt++)
#pragma unroll
                for (int nt = 0; nt < 4; nt++) {
                    mma_tf32(cg[mt][nt], af[mt], bg[nt]);
                    mma_tf32(cu[mt][nt], af[mt], bu[nt]);
                }
        }
        __syncthreads();
    }

    // epilogue: SwiGLU, write g_act (perm order)
#pragma unroll
    for (int mt = 0; mt < 2; mt++) {
#pragma unroll
        for (int rr = 0; rr < 2; rr++) {
            int m = m0 + wm * 32 + mt * 16 + gid + rr * 8;
            if (m < cnt) {
                float* op = g_act + (size_t)(base + m) * I_ + (size_t)(i0 + wn * 32) + 2 * tig;
#pragma unroll
                for (int nt = 0; nt < 4; nt++) {
                    float g0 = cg[mt][nt][2 * rr],     u0 = cu[mt][nt][2 * rr];
                    float g1 = cg[mt][nt][2 * rr + 1], u1 = cu[mt][nt][2 * rr + 1];
                    float2 v;
                    v.x = (g0 / (1.0f + __expf(-g0))) * u0;
                    v.y = (g1 / (1.0f + __expf(-g1))) * u1;
                    *(float2*)(op + nt * 8) = v;
                }
            }
        }
    }
}

// =================================================================================
// GEMM2: y[a, h0..h0+128) = act @ w2^T.  M=128 x N=128, 8 warps = 2M x 4N.
// 3-stage cp.async pipeline, 2 CTAs/SM.
// =================================================================================
__global__ __launch_bounds__(256, 2)
void gemm2_tc(const float* __restrict__ w2)
{
    constexpr int KT = I_;
    constexpr int NS = KT / 32;   // 176 stages

    extern __shared__ char sm[];
    int* s_row = (int*)(sm + STAGES * STG_BYTES);

    const int e = blockIdx.z;
    const int base = g_offs[e];
    const int cnt = g_offs[e + 1] - base;
    const int m0 = blockIdx.y * 128;
    if (m0 >= cnt) return;
    const int n0 = blockIdx.x * 128;

    const int tid = threadIdx.x;
    const int wid = tid >> 5, lid = tid & 31;
    const int gid = lid >> 2, tig = lid & 3;
    const int wm = wid & 1, wn = wid >> 1;   // 2M x 4N

    if (tid < 128) {
        int m = m0 + tid;
        s_row[tid] = base + ((m < cnt) ? m : 0);
    }
    __syncthreads();

    const float* ap[4]; const float* bp[4]; uint32_t so[4];
#pragma unroll
    for (int t = 0; t < 4; t++) {
        int idx = t * 256 + tid;
        int row = idx >> 3, q = idx & 7;
        so[t] = (uint32_t)(row * 128 + ((q ^ (row & 7)) << 4));
        ap[t] = g_act + (size_t)s_row[row] * KT + q * 4;
        bp[t] = w2 + ((size_t)e * H_ + (size_t)(n0 + row)) * KT + q * 4;
    }

    const uint32_t smbase = smem_u32(sm);
    auto issue = [&](int stage) {
        uint32_t ab = smbase + (uint32_t)(stage % STAGES) * STG_BYTES;
        uint32_t bb = ab + 16384;
#pragma unroll
        for (int t = 0; t < 4; t++) {
            CP_ASYNC16(ab + so[t], ap[t]);
            CP_ASYNC16(bb + so[t], bp[t]);
            ap[t] += 32; bp[t] += 32;
        }
    };

#pragma unroll
    for (int p = 0; p < STAGES - 1; p++) { issue(p); CP_COMMIT(); }

    float c[4][4][4] = {};

    for (int s = 0; s < NS; s++) {
        CP_WAIT(STAGES - 2);
        __syncthreads();
        if (s + STAGES - 1 < NS) issue(s + STAGES - 1);
        CP_COMMIT();

        const char* A = sm + (s % STAGES) * STG_BYTES;
        const char* B = A + 16384;
#pragma unroll
        for (int kt = 0; kt < 4; kt++) {
            uint32_t af[4][4], bf[4][2];
#pragma unroll
            for (int mt = 0; mt < 4; mt++) {
                int rbase = wm * 64 + mt * 16 + gid;
#pragma unroll
                for (int cc = 0; cc < 2; cc++) {
                    int k = kt * 8 + tig + cc * 4;
                    af[mt][0 + 2 * cc] = f2t(*(const float*)(A + tswz(rbase,     k)));
                    af[mt][1 + 2 * cc] = f2t(*(const float*)(A + tswz(rbase + 8, k)));
                }
            }
#pragma unroll
            for (int nt = 0; nt < 4; nt++) {
                int n = wn * 32 + nt * 8 + gid;
                bf[nt][0] = f2t(*(const float*)(B + tswz(n, kt * 8 + tig)));
                bf[nt][1] = f2t(*(const float*)(B + tswz(n, kt * 8 + tig + 4)));
            }
#pragma unroll
            for (int mt = 0; mt < 4; mt++)
#pragma unroll
                for (int nt = 0; nt < 4; nt++)
                    mma_tf32(c[mt][nt], af[mt], bf[nt]);
        }
        __syncthreads();
    }

#pragma unroll
    for (int mt = 0; mt < 4; mt++) {
#pragma unroll
        for (int rr = 0; rr < 2; rr++) {
            int m = m0 + wm * 64 + mt * 16 + gid + rr * 8;
            if (m < cnt) {
                int orow = g_perm[base + m];
                float* op = g_y + (size_t)orow * H_ + (size_t)(n0 + wn * 32) + 2 * tig;
#pragma unroll
                for (int nt = 0; nt < 4; nt++) {
                    float2 v = make_float2(c[mt][nt][2 * rr], c[mt][nt][2 * rr + 1]);
                    *(float2*)(op + nt * 8) = v;
                }
            }
        }
    }
}

// ---------------- combine: out[t,h] = w0*y[2t,h] + w1*y[2t+1,h] ----------------
__global__ void combine_kernel(float* __restrict__ out) {
    int idx = blockIdx.x * blockDim.x + threadIdx.x;
    int t  = idx >> 9;
    int h4 = idx & 511;
    float w0 = g_aw[2 * t];
    float w1 = g_aw[2 * t + 1];
    float4 y0 = *(const float4*)&g_y[(size_t)(2 * t)     * H_ + (size_t)h4 * 4];
    float4 y1 = *(const float4*)&g_y[(size_t)(2 * t + 1) * H_ + (size_t)h4 * 4];
    float4 o;
    o.x = w0 * y0.x + w1 * y1.x;
    o.y = w0 * y0.y + w1 * y1.y;
    o.z = w0 * y0.z + w1 * y1.z;
    o.w = w0 * y0.w + w1 * y1.w;
    *(float4*)&out[(size_t)t * H_ + (size_t)h4 * 4] = o;
}

extern "C" void kernel_launch(void* const* d_in, const int* in_sizes, int n_in,
                              void* d_out, int out_size) {
    const float* x   = (const float*)d_in[0];   // [512, 2048]
    const float* rl  = (const float*)d_in[1];   // [512, 8]
    const float* w13 = (const float*)d_in[2];   // [8, 11264, 2048]
    const float* w2  = (const float*)d_in[3];   // [8, 2048, 5632]
    float* out = (float*)d_out;                 // [512, 2048]
    (void)in_sizes; (void)n_in; (void)out_size;

    cudaFuncSetAttribute(gemm1_fused, cudaFuncAttributeMaxDynamicSharedMemorySize, GM_SMEM);
    cudaFuncSetAttribute(gemm2_tc,    cudaFuncAttributeMaxDynamicSharedMemorySize, GM_SMEM);

    route_kernel<<<1, T_>>>(rl);
    // GEMM1 fused: grid.y = 4 covers worst case (512 tokens on one expert)
    gemm1_fused<<<dim3(I_ / 64, 4, E_), 256, GM_SMEM>>>(x, w13);
    // GEMM2: act @ w2^T -> g_y (scatter to assignment order)
    gemm2_tc<<<dim3(H_ / 128, 4, E_), 256, GM_SMEM>>>(w2);
    combine_kernel<<<(T_ * H_ / 4) / 512, 512>>>(out);
}

// round 7
// speedup vs baseline: 3.7141x; 1.1354x over previous
#include <cuda_runtime.h>
#include <cstdint>
#include <math.h>

// Problem constants
#define T_ 512
#define E_ 8
#define H_ 2048
#define I_ 5632
#define A_ (2 * T_)   // 1024 token-expert assignments (top_k = 2)
#define SPLITK 4
#define K2_PER (I_ / SPLITK)   // 1408

// ---------------- scratch (device globals; no allocation allowed) ----------------
__device__ float g_act[(size_t)A_ * I_];            // SwiGLU activations, perm order
__device__ float g_part[(size_t)SPLITK * A_ * H_];  // split-K partials of down-proj
__device__ int   g_perm[A_];                        // assignment ids grouped by expert
__device__ int   g_offs[E_ + 1];                    // expert segment offsets
__device__ float g_aw[A_];                          // renormalized top-2 weights

// ---------------- helpers ----------------
__device__ __forceinline__ uint32_t pack_h2(float2 v) {  // {lo=v.x, hi=v.y} as f16x2
    uint32_t r;
    asm("cvt.rn.f16x2.f32 %0, %1, %2;" : "=r"(r) : "f"(v.y), "f"(v.x));
    return r;
}
__device__ __forceinline__ void mma_f16(float* d, const uint32_t* a, const uint32_t* b) {
    asm volatile(
        "mma.sync.aligned.m16n8k16.row.col.f32.f16.f16.f32 "
        "{%0,%1,%2,%3}, {%4,%5,%6,%7}, {%8,%9}, {%0,%1,%2,%3};"
        : "+f"(d[0]), "+f"(d[1]), "+f"(d[2]), "+f"(d[3])
        : "r"(a[0]), "r"(a[1]), "r"(a[2]), "r"(a[3]), "r"(b[0]), "r"(b[1]));
}
__device__ __forceinline__ uint32_t smem_u32(const void* p) {
    return (uint32_t)__cvta_generic_to_shared(p);
}
#define CP_ASYNC16(dst, src) \
    asm volatile("cp.async.cg.shared.global [%0], [%1], 16;" :: "r"(dst), "l"(src))
#define CP_COMMIT() asm volatile("cp.async.commit_group;" ::: "memory")
#define CP_WAIT(n)  asm volatile("cp.async.wait_group %0;" :: "n"(n) : "memory")

// swizzled byte offset inside a (rows x 32-float) tile: 128B rows, 16B chunk XOR
__device__ __forceinline__ uint32_t tswz(int row, int k) {
    return (uint32_t)(row * 128 + (((k >> 2) ^ (row & 7)) << 4) + ((k & 3) << 2));
}
// load adjacent float pair (k, k+1), k even — always within one 16B chunk
__device__ __forceinline__ float2 lds2(const char* base, int row, int k) {
    return *(const float2*)(base + tswz(row, k));
}

// ---------------- routing ----------------
__global__ void route_kernel(const float* __restrict__ logits) {
    __shared__ unsigned char s_e[A_];
    __shared__ int s_cnt[E_];
    __shared__ int s_off[E_ + 1];

    int t = threadIdx.x;
    if (t < E_) s_cnt[t] = 0;
    __syncthreads();

    float l[E_];
#pragma unroll
    for (int e = 0; e < E_; e++) l[e] = logits[t * E_ + e];

    int e0 = 0;
#pragma unroll
    for (int e = 1; e < E_; e++) if (l[e] > l[e0]) e0 = e;
    int e1 = (e0 == 0) ? 1 : 0;
#pragma unroll
    for (int e = 0; e < E_; e++) if (e != e0 && l[e] > l[e1]) e1 = e;

    float p1 = __expf(l[e1] - l[e0]);
    float inv = 1.0f / (1.0f + p1);
    g_aw[2 * t + 0] = inv;
    g_aw[2 * t + 1] = p1 * inv;

    s_e[2 * t + 0] = (unsigned char)e0;
    s_e[2 * t + 1] = (unsigned char)e1;
    atomicAdd(&s_cnt[e0], 1);
    atomicAdd(&s_cnt[e1], 1);
    __syncthreads();

    if (t == 0) {
        int acc = 0;
        for (int e = 0; e < E_; e++) { s_off[e] = acc; acc += s_cnt[e]; }
        s_off[E_] = acc;
        for (int e = 0; e <= E_; e++) g_offs[e] = s_off[e];
    }
    __syncthreads();

#pragma unroll
    for (int k = 0; k < 2; k++) {
        int a = 2 * t + k;
        int e = s_e[a];
        int rank = 0;
        for (int b = 0; b < a; b++) rank += (s_e[b] == e) ? 1 : 0;
        g_perm[s_off[e] + rank] = a;
    }
}

#define STAGES 3
#define STG_BYTES 32768
#define GM_SMEM (STAGES * STG_BYTES + 512)

// =================================================================================
// GEMM1 fused (fp16 mma): act[m, i0..i0+64) = silu(x@Wg^T) * (x@Wu^T) per expert.
// CTA: M=128, N=64 gate + N=64 up. 8 warps = 4M x 2N, warp tile 32x32 (x2 g/u).
// K=32/stage; smem/stage: A 16KB | Bg 8KB | Bu 8KB (raw fp32; cvt to f16 at read).
// =================================================================================
__global__ __launch_bounds__(256, 2)
void gemm1_fused(const float* __restrict__ x, const float* __restrict__ w13)
{
    constexpr int KT = H_;
    constexpr int NS = KT / 32;   // 64 stages

    extern __shared__ char sm[];
    int* s_row = (int*)(sm + STAGES * STG_BYTES);

    const int e = blockIdx.z;
    const int base = g_offs[e];
    const int cnt = g_offs[e + 1] - base;
    const int m0 = blockIdx.y * 128;
    if (m0 >= cnt) return;
    const int i0 = blockIdx.x * 64;

    const int tid = threadIdx.x;
    const int wid = tid >> 5, lid = tid & 31;
    const int gid = lid >> 2, tig = lid & 3;
    const int wm = wid >> 1, wn = wid & 1;   // 4M x 2N

    if (tid < 128) {
        int m = m0 + tid;
        int mm = (m < cnt) ? m : 0;
        s_row[tid] = g_perm[base + mm] >> 1;
    }
    __syncthreads();

    const float* ap[4]; uint32_t soA[4];
    const float* gp[2]; const float* up[2]; uint32_t soB[2];
#pragma unroll
    for (int t = 0; t < 4; t++) {
        int idx = t * 256 + tid;
        int row = idx >> 3, q = idx & 7;
        soA[t] = (uint32_t)(row * 128 + ((q ^ (row & 7)) << 4));
        ap[t] = x + (size_t)s_row[row] * KT + q * 4;
    }
#pragma unroll
    for (int t = 0; t < 2; t++) {
        int idx = t * 256 + tid;
        int row = idx >> 3, q = idx & 7;   // row 0..63
        soB[t] = (uint32_t)(row * 128 + ((q ^ (row & 7)) << 4));
        gp[t] = w13 + ((size_t)e * (2 * I_) + (size_t)(i0 + row)) * KT + q * 4;
        up[t] = w13 + ((size_t)e * (2 * I_) + (size_t)(I_ + i0 + row)) * KT + q * 4;
    }

    const uint32_t smbase = smem_u32(sm);
    auto issue = [&](int stage) {
        uint32_t ab = smbase + (uint32_t)(stage % STAGES) * STG_BYTES;
        uint32_t gb = ab + 16384;
        uint32_t ub = gb + 8192;
#pragma unroll
        for (int t = 0; t < 4; t++) { CP_ASYNC16(ab + soA[t], ap[t]); ap[t] += 32; }
#pragma unroll
        for (int t = 0; t < 2; t++) {
            CP_ASYNC16(gb + soB[t], gp[t]); gp[t] += 32;
            CP_ASYNC16(ub + soB[t], up[t]); up[t] += 32;
        }
    };

#pragma unroll
    for (int p = 0; p < STAGES - 1; p++) { issue(p); CP_COMMIT(); }

    float cg[2][4][4] = {}, cu[2][4][4] = {};

    for (int s = 0; s < NS; s++) {
        CP_WAIT(STAGES - 2);
        __syncthreads();
        if (s + STAGES - 1 < NS) issue(s + STAGES - 1);
        CP_COMMIT();

        const char* A  = sm + (s % STAGES) * STG_BYTES;
        const char* Bg = A + 16384;
        const char* Bu = Bg + 8192;
#pragma unroll
        for (int kt = 0; kt < 2; kt++) {           // two k16 groups per 32-K stage
            const int k0 = kt * 16 + 2 * tig;
            uint32_t af[2][4], bg[4][2], bu[4][2];
#pragma unroll
            for (int mt = 0; mt < 2; mt++) {
                int rbase = wm * 32 + mt * 16 + gid;
                af[mt][0] = pack_h2(lds2(A, rbase,     k0));
                af[mt][1] = pack_h2(lds2(A, rbase + 8, k0));
                af[mt][2] = pack_h2(lds2(A, rbase,     k0 + 8));
                af[mt][3] = pack_h2(lds2(A, rbase + 8, k0 + 8));
            }
#pragma unroll
            for (int nt = 0; nt < 4; nt++) {
                int n = wn * 32 + nt * 8 + gid;
                bg[nt][0] = pack_h2(lds2(Bg, n, k0));
                bg[nt][1] = pack_h2(lds2(Bg, n, k0 + 8));
                bu[nt][0] = pack_h2(lds2(Bu, n, k0));
                bu[nt][1] = pack_h2(lds2(Bu, n, k0 + 8));
            }
#pragma unroll
            for (int mt = 0; mt < 2; mt++)
#pragma unroll
                for (int nt = 0; nt < 4; nt++) {
                    mma_f16(cg[mt][nt], af[mt], bg[nt]);
                    mma_f16(cu[mt][nt], af[mt], bu[nt]);
                }
        }
        __syncthreads();
    }

    // epilogue: SwiGLU, write g_act (perm order)
#pragma unroll
    for (int mt = 0; mt < 2; mt++) {
#pragma unroll
        for (int rr = 0; rr < 2; rr++) {
            int m = m0 + wm * 32 + mt * 16 + gid + rr * 8;
            if (m < cnt) {
                float* op = g_act + (size_t)(base + m) * I_ + (size_t)(i0 + wn * 32) + 2 * tig;
#pragma unroll
                for (int nt = 0; nt < 4; nt++) {
                    float g0 = cg[mt][nt][2 * rr],     u0 = cu[mt][nt][2 * rr];
                    float g1 = cg[mt][nt][2 * rr + 1], u1 = cu[mt][nt][2 * rr + 1];
                    float2 v;
                    v.x = (g0 / (1.0f + __expf(-g0))) * u0;
                    v.y = (g1 / (1.0f + __expf(-g1))) * u1;
                    *(float2*)(op + nt * 8) = v;
                }
            }
        }
    }
}

// =================================================================================
// GEMM2 (fp16 mma, split-K=4): part[sk][a, h0..h0+128) = act[:, kr] @ w2[:, kr]^T.
// CTA: M=128 x N=128, 8 warps = 2M x 4N (64x32 per warp). K range = 1408 (44 stages).
// =================================================================================
__global__ __launch_bounds__(256, 2)
void gemm2_tc(const float* __restrict__ w2)
{
    constexpr int KT = I_;
    constexpr int NS = K2_PER / 32;   // 44 stages per split

    extern __shared__ char sm[];
    int* s_row = (int*)(sm + STAGES * STG_BYTES);

    const int e  = blockIdx.z >> 2;
    const int sk = blockIdx.z & 3;
    const int base = g_offs[e];
    const int cnt = g_offs[e + 1] - base;
    const int m0 = blockIdx.y * 128;
    if (m0 >= cnt) return;
    const int n0 = blockIdx.x * 128;
    const int koff = sk * K2_PER;

    const int tid = threadIdx.x;
    const int wid = tid >> 5, lid = tid & 31;
    const int gid = lid >> 2, tig = lid & 3;
    const int wm = wid & 1, wn = wid >> 1;   // 2M x 4N

    if (tid < 128) {
        int m = m0 + tid;
        s_row[tid] = base + ((m < cnt) ? m : 0);
    }
    __syncthreads();

    const float* ap[4]; const float* bp[4]; uint32_t so[4];
#pragma unroll
    for (int t = 0; t < 4; t++) {
        int idx = t * 256 + tid;
        int row = idx >> 3, q = idx & 7;
        so[t] = (uint32_t)(row * 128 + ((q ^ (row & 7)) << 4));
        ap[t] = g_act + (size_t)s_row[row] * KT + koff + q * 4;
        bp[t] = w2 + ((size_t)e * H_ + (size_t)(n0 + row)) * KT + koff + q * 4;
    }

    const uint32_t smbase = smem_u32(sm);
    auto issue = [&](int stage) {
        uint32_t ab = smbase + (uint32_t)(stage % STAGES) * STG_BYTES;
        uint32_t bb = ab + 16384;
#pragma unroll
        for (int t = 0; t < 4; t++) {
            CP_ASYNC16(ab + so[t], ap[t]);
            CP_ASYNC16(bb + so[t], bp[t]);
            ap[t] += 32; bp[t] += 32;
        }
    };

#pragma unroll
    for (int p = 0; p < STAGES - 1; p++) { issue(p); CP_COMMIT(); }

    float c[4][4][4] = {};

    for (int s = 0; s < NS; s++) {
        CP_WAIT(STAGES - 2);
        __syncthreads();
        if (s + STAGES - 1 < NS) issue(s + STAGES - 1);
        CP_COMMIT();

        const char* A = sm + (s % STAGES) * STG_BYTES;
        const char* B = A + 16384;
#pragma unroll
        for (int kt = 0; kt < 2; kt++) {
            const int k0 = kt * 16 + 2 * tig;
            uint32_t af[4][4], bf[4][2];
#pragma unroll
            for (int mt = 0; mt < 4; mt++) {
                int rbase = wm * 64 + mt * 16 + gid;
                af[mt][0] = pack_h2(lds2(A, rbase,     k0));
                af[mt][1] = pack_h2(lds2(A, rbase + 8, k0));
                af[mt][2] = pack_h2(lds2(A, rbase,     k0 + 8));
                af[mt][3] = pack_h2(lds2(A, rbase + 8, k0 + 8));
            }
#pragma unroll
            for (int nt = 0; nt < 4; nt++) {
                int n = wn * 32 + nt * 8 + gid;
                bf[nt][0] = pack_h2(lds2(B, n, k0));
                bf[nt][1] = pack_h2(lds2(B, n, k0 + 8));
            }
#pragma unroll
            for (int mt = 0; mt < 4; mt++)
#pragma unroll
                for (int nt = 0; nt < 4; nt++)
                    mma_f16(c[mt][nt], af[mt], bf[nt]);
        }
        __syncthreads();
    }

    // epilogue: write split partial (assignment-id rows)
    float* part = g_part + (size_t)sk * A_ * H_;
#pragma unroll
    for (int mt = 0; mt < 4; mt++) {
#pragma unroll
        for (int rr = 0; rr < 2; rr++) {
            int m = m0 + wm * 64 + mt * 16 + gid + rr * 8;
            if (m < cnt) {
                int orow = g_perm[base + m];
                float* op = part + (size_t)orow * H_ + (size_t)(n0 + wn * 32) + 2 * tig;
#pragma unroll
                for (int nt = 0; nt < 4; nt++) {
                    float2 v = make_float2(c[mt][nt][2 * rr], c[mt][nt][2 * rr + 1]);
                    *(float2*)(op + nt * 8) = v;
                }
            }
        }
    }
}

// ---------------- combine: out[t,h] = sum_k aw * sum_s part[s][2t+k][h] -----------
__global__ void combine_kernel(float* __restrict__ out) {
    int idx = blockIdx.x * blockDim.x + threadIdx.x;
    int t  = idx >> 9;
    int h4 = idx & 511;
    float w0 = g_aw[2 * t];
    float w1 = g_aw[2 * t + 1];
    size_t o0 = (size_t)(2 * t) * H_ + (size_t)h4 * 4;
    size_t o1 = (size_t)(2 * t + 1) * H_ + (size_t)h4 * 4;

    float4 a0 = make_float4(0.f, 0.f, 0.f, 0.f);
    float4 a1 = make_float4(0.f, 0.f, 0.f, 0.f);
#pragma unroll
    for (int s = 0; s < SPLITK; s++) {   // fixed order -> deterministic
        const float* p = g_part + (size_t)s * A_ * H_;
        float4 v0 = *(const float4*)(p + o0);
        float4 v1 = *(const float4*)(p + o1);
        a0.x += v0.x; a0.y += v0.y; a0.z += v0.z; a0.w += v0.w;
        a1.x += v1.x; a1.y += v1.y; a1.z += v1.z; a1.w += v1.w;
    }
    float4 o;
    o.x = w0 * a0.x + w1 * a1.x;
    o.y = w0 * a0.y + w1 * a1.y;
    o.z = w0 * a0.z + w1 * a1.z;
    o.w = w0 * a0.w + w1 * a1.w;
    *(float4*)&out[(size_t)t * H_ + (size_t)h4 * 4] = o;
}

extern "C" void kernel_launch(void* const* d_in, const int* in_sizes, int n_in,
                              void* d_out, int out_size) {
    const float* x   = (const float*)d_in[0];   // [512, 2048]
    const float* rl  = (const float*)d_in[1];   // [512, 8]
    const float* w13 = (const float*)d_in[2];   // [8, 11264, 2048]
    const float* w2  = (const float*)d_in[3];   // [8, 2048, 5632]
    float* out = (float*)d_out;                 // [512, 2048]
    (void)in_sizes; (void)n_in; (void)out_size;

    cudaFuncSetAttribute(gemm1_fused, cudaFuncAttributeMaxDynamicSharedMemorySize, GM_SMEM);
    cudaFuncSetAttribute(gemm2_tc,    cudaFuncAttributeMaxDynamicSharedMemorySize, GM_SMEM);

    route_kernel<<<1, T_>>>(rl);
    // GEMM1 fused: grid.y = 4 covers worst case (512 tokens on one expert)
    gemm1_fused<<<dim3(I_ / 64, 4, E_), 256, GM_SMEM>>>(x, w13);
    // GEMM2 split-K: z = e*4 + sk
    gemm2_tc<<<dim3(H_ / 128, 4, E_ * SPLITK), 256, GM_SMEM>>>(w2);
    combine_kernel<<<(T_ * H_ / 4) / 512, 512>>>(out);
}

// round 8
// speedup vs baseline: 3.9276x; 1.0575x over previous
#include <cuda_runtime.h>
#include <cuda_fp16.h>
#include <cstdint>
#include <math.h>

// Problem constants
#define T_ 512
#define E_ 8
#define H_ 2048
#define I_ 5632
#define A_ (2 * T_)   // 1024 token-expert assignments (top_k = 2)
#define SPLITK 4
#define K2_PER (I_ / SPLITK)   // 1408

// ---------------- scratch (device globals; no allocation allowed) ----------------
__device__ __half g_xh[(size_t)T_ * H_];            // x converted to fp16
__device__ __half g_acth[(size_t)A_ * I_];          // SwiGLU activations fp16, perm order
__device__ float  g_part[(size_t)SPLITK * A_ * H_]; // split-K partials of down-proj
__device__ int    g_perm[A_];                       // assignment ids grouped by expert
__device__ int    g_offs[E_ + 1];                   // expert segment offsets
__device__ float  g_aw[A_];                         // renormalized top-2 weights

// ---------------- helpers ----------------
__device__ __forceinline__ uint32_t pack_h2(float2 v) {  // {lo=v.x, hi=v.y} as f16x2
    uint32_t r;
    asm("cvt.rn.f16x2.f32 %0, %1, %2;" : "=r"(r) : "f"(v.y), "f"(v.x));
    return r;
}
__device__ __forceinline__ void mma_f16(float* d, const uint32_t* a, const uint32_t* b) {
    asm volatile(
        "mma.sync.aligned.m16n8k16.row.col.f32.f16.f16.f32 "
        "{%0,%1,%2,%3}, {%4,%5,%6,%7}, {%8,%9}, {%0,%1,%2,%3};"
        : "+f"(d[0]), "+f"(d[1]), "+f"(d[2]), "+f"(d[3])
        : "r"(a[0]), "r"(a[1]), "r"(a[2]), "r"(a[3]), "r"(b[0]), "r"(b[1]));
}
__device__ __forceinline__ uint32_t smem_u32(const void* p) {
    return (uint32_t)__cvta_generic_to_shared(p);
}
#define CP_ASYNC16(dst, src) \
    asm volatile("cp.async.cg.shared.global [%0], [%1], 16;" :: "r"(dst), "l"(src))
#define CP_COMMIT() asm volatile("cp.async.commit_group;" ::: "memory")
#define CP_WAIT(n)  asm volatile("cp.async.wait_group %0;" :: "n"(n) : "memory")

// swizzled byte offset inside a (rows x 32-float) fp32 tile: 128B rows, 16B chunk XOR
__device__ __forceinline__ uint32_t tswz(int row, int k) {
    return (uint32_t)(row * 128 + (((k >> 2) ^ (row & 7)) << 4) + ((k & 3) << 2));
}
// load adjacent fp32 pair (k, k+1), k even — always within one 16B chunk
__device__ __forceinline__ float2 lds2(const char* base, int row, int k) {
    return *(const float2*)(base + tswz(row, k));
}

// fp16 A tile: 128 rows x 32 halves (64B data), padded row stride 80B (conflict-free)
#define AROW 80

// ---------------- x -> fp16 ----------------
__global__ void xcvt_kernel(const float* __restrict__ x) {
    int i = blockIdx.x * blockDim.x + threadIdx.x;   // over T_*H_/2 half2
    float2 v = *(const float2*)&x[2 * i];
    *(uint32_t*)&g_xh[2 * i] = pack_h2(v);
}

// ---------------- routing ----------------
__global__ void route_kernel(const float* __restrict__ logits) {
    __shared__ unsigned char s_e[A_];
    __shared__ int s_cnt[E_];
    __shared__ int s_off[E_ + 1];

    int t = threadIdx.x;
    if (t < E_) s_cnt[t] = 0;
    __syncthreads();

    float l[E_];
#pragma unroll
    for (int e = 0; e < E_; e++) l[e] = logits[t * E_ + e];

    int e0 = 0;
#pragma unroll
    for (int e = 1; e < E_; e++) if (l[e] > l[e0]) e0 = e;
    int e1 = (e0 == 0) ? 1 : 0;
#pragma unroll
    for (int e = 0; e < E_; e++) if (e != e0 && l[e] > l[e1]) e1 = e;

    float p1 = __expf(l[e1] - l[e0]);
    float inv = 1.0f / (1.0f + p1);
    g_aw[2 * t + 0] = inv;
    g_aw[2 * t + 1] = p1 * inv;

    s_e[2 * t + 0] = (unsigned char)e0;
    s_e[2 * t + 1] = (unsigned char)e1;
    atomicAdd(&s_cnt[e0], 1);
    atomicAdd(&s_cnt[e1], 1);
    __syncthreads();

    if (t == 0) {
        int acc = 0;
        for (int e = 0; e < E_; e++) { s_off[e] = acc; acc += s_cnt[e]; }
        s_off[E_] = acc;
        for (int e = 0; e <= E_; e++) g_offs[e] = s_off[e];
    }
    __syncthreads();

#pragma unroll
    for (int k = 0; k < 2; k++) {
        int a = 2 * t + k;
        int e = s_e[a];
        int rank = 0;
        for (int b = 0; b < a; b++) rank += (s_e[b] == e) ? 1 : 0;
        g_perm[s_off[e] + rank] = a;
    }
}

// =================================================================================
// GEMM1 fused: act[m, i0..i0+64) = silu(x@Wg^T)*(x@Wu^T).  A fp16, B fp32->f16 pack.
// CTA: M=128, N=64 gate + 64 up. 8 warps = 4M x 2N, warp 32x32 (x2 g/u).
// Stage (K=32): A 10240B | Bg 8192B | Bu 8192B = 26624B. 3 stages.
// =================================================================================
#define S1 3
#define STG1 26624
#define G1_SMEM (S1 * STG1 + 512)

__global__ __launch_bounds__(256, 2)
void gemm1_fused(const float* __restrict__ w13)
{
    constexpr int NS = H_ / 32;   // 64 stages

    extern __shared__ char sm[];
    int* s_row = (int*)(sm + S1 * STG1);

    const int e = blockIdx.z;
    const int base = g_offs[e];
    const int cnt = g_offs[e + 1] - base;
    const int m0 = blockIdx.y * 128;
    if (m0 >= cnt) return;
    const int i0 = blockIdx.x * 64;

    const int tid = threadIdx.x;
    const int wid = tid >> 5, lid = tid & 31;
    const int gid = lid >> 2, tig = lid & 3;
    const int wm = wid >> 1, wn = wid & 1;   // 4M x 2N

    if (tid < 128) {
        int m = m0 + tid;
        int mm = (m < cnt) ? m : 0;
        s_row[tid] = g_perm[base + mm] >> 1;
    }
    __syncthreads();

    // A: 512 16B-chunks -> 2/thread.  Bg/Bu: 512 chunks each -> 2/thread each.
    const char* ap[2]; uint32_t soA[2];
    const float* gp[2]; const float* up[2]; uint32_t soB[2];
#pragma unroll
    for (int t = 0; t < 2; t++) {
        int idx = t * 256 + tid;
        int row = idx >> 2, q = idx & 3;
        soA[t] = (uint32_t)(row * AROW + q * 16);
        ap[t] = (const char*)(g_xh + (size_t)s_row[row] * H_) + q * 16;
    }
#pragma unroll
    for (int t = 0; t < 2; t++) {
        int idx = t * 256 + tid;
        int row = idx >> 3, q = idx & 7;   // row 0..63
        soB[t] = (uint32_t)(row * 128 + ((q ^ (row & 7)) << 4));
        gp[t] = w13 + ((size_t)e * (2 * I_) + (size_t)(i0 + row)) * H_ + q * 4;
        up[t] = w13 + ((size_t)e * (2 * I_) + (size_t)(I_ + i0 + row)) * H_ + q * 4;
    }

    const uint32_t smbase = smem_u32(sm);
    auto issue = [&](int stage) {
        uint32_t ab = smbase + (uint32_t)(stage % S1) * STG1;
        uint32_t gb = ab + 10240;
        uint32_t ub = gb + 8192;
#pragma unroll
        for (int t = 0; t < 2; t++) { CP_ASYNC16(ab + soA[t], ap[t]); ap[t] += 64; }
#pragma unroll
        for (int t = 0; t < 2; t++) {
            CP_ASYNC16(gb + soB[t], gp[t]); gp[t] += 32;
            CP_ASYNC16(ub + soB[t], up[t]); up[t] += 32;
        }
    };

#pragma unroll
    for (int p = 0; p < S1 - 1; p++) { issue(p); CP_COMMIT(); }

    float cg[2][4][4] = {}, cu[2][4][4] = {};

    for (int s = 0; s < NS; s++) {
        CP_WAIT(S1 - 2);
        __syncthreads();               // stage s resident; prev buffer free
        if (s + S1 - 1 < NS) issue(s + S1 - 1);
        CP_COMMIT();

        const char* A  = sm + (s % S1) * STG1;
        const char* Bg = A + 10240;
        const char* Bu = Bg + 8192;
#pragma unroll
        for (int kt = 0; kt < 2; kt++) {
            uint32_t af[2][4], bg[4][2], bu[4][2];
#pragma unroll
            for (int mt = 0; mt < 2; mt++) {
                int rbase = wm * 32 + mt * 16 + gid;
                const char* p0 = A + rbase * AROW + kt * 32 + tig * 4;
                af[mt][0] = *(const uint32_t*)(p0);
                af[mt][1] = *(const uint32_t*)(p0 + 8 * AROW);
                af[mt][2] = *(const uint32_t*)(p0 + 16);
                af[mt][3] = *(const uint32_t*)(p0 + 8 * AROW + 16);
            }
            const int k0 = kt * 16 + 2 * tig;
#pragma unroll
            for (int nt = 0; nt < 4; nt++) {
                int n = wn * 32 + nt * 8 + gid;
                bg[nt][0] = pack_h2(lds2(Bg, n, k0));
                bg[nt][1] = pack_h2(lds2(Bg, n, k0 + 8));
                bu[nt][0] = pack_h2(lds2(Bu, n, k0));
                bu[nt][1] = pack_h2(lds2(Bu, n, k0 + 8));
            }
#pragma unroll
            for (int mt = 0; mt < 2; mt++)
#pragma unroll
                for (int nt = 0; nt < 4; nt++) {
                    mma_f16(cg[mt][nt], af[mt], bg[nt]);
                    mma_f16(cu[mt][nt], af[mt], bu[nt]);
                }
        }
    }

    // epilogue: SwiGLU, write g_acth fp16 (perm order)
#pragma unroll
    for (int mt = 0; mt < 2; mt++) {
#pragma unroll
        for (int rr = 0; rr < 2; rr++) {
            int m = m0 + wm * 32 + mt * 16 + gid + rr * 8;
            if (m < cnt) {
                __half* op = g_acth + (size_t)(base + m) * I_ + (size_t)(i0 + wn * 32) + 2 * tig;
#pragma unroll
                for (int nt = 0; nt < 4; nt++) {
                    float g0 = cg[mt][nt][2 * rr],     u0 = cu[mt][nt][2 * rr];
                    float g1 = cg[mt][nt][2 * rr + 1], u1 = cu[mt][nt][2 * rr + 1];
                    float2 v;
                    v.x = (g0 / (1.0f + __expf(-g0))) * u0;
                    v.y = (g1 / (1.0f + __expf(-g1))) * u1;
                    *(uint32_t*)(op + nt * 8) = pack_h2(v);
                }
            }
        }
    }
}

// =================================================================================
// GEMM2 (split-K=4): part[sk][a, h0..h0+128) = act_fp16 @ w2^T.
// CTA: M=128 x N=128, 8 warps = 2M x 4N (64x32/warp). K range 1408 (44 stages).
// Stage: A fp16 10240B | B fp32 16384B = 26624B. 4 stages.
// =================================================================================
#define S2 4
#define STG2 26624
#define G2_SMEM (S2 * STG2 + 512)

__global__ __launch_bounds__(256, 2)
void gemm2_tc(const float* __restrict__ w2)
{
    constexpr int NS = K2_PER / 32;   // 44 stages

    extern __shared__ char sm[];
    int* s_row = (int*)(sm + S2 * STG2);

    const int e  = blockIdx.z >> 2;
    const int sk = blockIdx.z & 3;
    const int base = g_offs[e];
    const int cnt = g_offs[e + 1] - base;
    const int m0 = blockIdx.y * 128;
    if (m0 >= cnt) return;
    const int n0 = blockIdx.x * 128;
    const int koff = sk * K2_PER;

    const int tid = threadIdx.x;
    const int wid = tid >> 5, lid = tid & 31;
    const int gid = lid >> 2, tig = lid & 3;
    const int wm = wid & 1, wn = wid >> 1;   // 2M x 4N

    if (tid < 128) {
        int m = m0 + tid;
        s_row[tid] = base + ((m < cnt) ? m : 0);
    }
    __syncthreads();

    // A: 512 chunks -> 2/thread.  B: 1024 chunks -> 4/thread.
    const char* ap[2]; uint32_t soA[2];
    const float* bp[4]; uint32_t soB[4];
#pragma unroll
    for (int t = 0; t < 2; t++) {
        int idx = t * 256 + tid;
        int row = idx >> 2, q = idx & 3;
        soA[t] = (uint32_t)(row * AROW + q * 16);
        ap[t] = (const char*)(g_acth + (size_t)s_row[row] * I_ + koff) + q * 16;
    }
#pragma unroll
    for (int t = 0; t < 4; t++) {
        int idx = t * 256 + tid;
        int row = idx >> 3, q = idx & 7;
        soB[t] = (uint32_t)(row * 128 + ((q ^ (row & 7)) << 4));
        bp[t] = w2 + ((size_t)e * H_ + (size_t)(n0 + row)) * I_ + koff + q * 4;
    }

    const uint32_t smbase = smem_u32(sm);
    auto issue = [&](int stage) {
        uint32_t ab = smbase + (uint32_t)(stage % S2) * STG2;
        uint32_t bb = ab + 10240;
#pragma unroll
        for (int t = 0; t < 2; t++) { CP_ASYNC16(ab + soA[t], ap[t]); ap[t] += 64; }
#pragma unroll
        for (int t = 0; t < 4; t++) { CP_ASYNC16(bb + soB[t], bp[t]); bp[t] += 32; }
    };

#pragma unroll
    for (int p = 0; p < S2 - 1; p++) { issue(p); CP_COMMIT(); }

    float c[4][4][4] = {};

    for (int s = 0; s < NS; s++) {
        CP_WAIT(S2 - 2);
        __syncthreads();
        if (s + S2 - 1 < NS) issue(s + S2 - 1);
        CP_COMMIT();

        const char* A = sm + (s % S2) * STG2;
        const char* B = A + 10240;
#pragma unroll
        for (int kt = 0; kt < 2; kt++) {
            uint32_t af[4][4], bf[4][2];
#pragma unroll
            for (int mt = 0; mt < 4; mt++) {
                int rbase = wm * 64 + mt * 16 + gid;
                const char* p0 = A + rbase * AROW + kt * 32 + tig * 4;
                af[mt][0] = *(const uint32_t*)(p0);
                af[mt][1] = *(const uint32_t*)(p0 + 8 * AROW);
                af[mt][2] = *(const uint32_t*)(p0 + 16);
                af[mt][3] = *(const uint32_t*)(p0 + 8 * AROW + 16);
            }
            const int k0 = kt * 16 + 2 * tig;
#pragma unroll
            for (int nt = 0; nt < 4; nt++) {
                int n = wn * 32 + nt * 8 + gid;
                bf[nt][0] = pack_h2(lds2(B, n, k0));
                bf[nt][1] = pack_h2(lds2(B, n, k0 + 8));
            }
#pragma unroll
            for (int mt = 0; mt < 4; mt++)
#pragma unroll
                for (int nt = 0; nt < 4; nt++)
                    mma_f16(c[mt][nt], af[mt], bf[nt]);
        }
    }

    // epilogue: write split partial (assignment-id rows)
    float* part = g_part + (size_t)sk * A_ * H_;
#pragma unroll
    for (int mt = 0; mt < 4; mt++) {
#pragma unroll
        for (int rr = 0; rr < 2; rr++) {
            int m = m0 + wm * 64 + mt * 16 + gid + rr * 8;
            if (m < cnt) {
                int orow = g_perm[base + m];
                float* op = part + (size_t)orow * H_ + (size_t)(n0 + wn * 32) + 2 * tig;
#pragma unroll
                for (int nt = 0; nt < 4; nt++) {
                    float2 v = make_float2(c[mt][nt][2 * rr], c[mt][nt][2 * rr + 1]);
                    *(float2*)(op + nt * 8) = v;
                }
            }
        }
    }
}

// ---------------- combine: out[t,h] = sum_k aw * sum_s part[s][2t+k][h] -----------
__global__ void combine_kernel(float* __restrict__ out) {
    int idx = blockIdx.x * blockDim.x + threadIdx.x;
    int t  = idx >> 9;
    int h4 = idx & 511;
    float w0 = g_aw[2 * t];
    float w1 = g_aw[2 * t + 1];
    size_t o0 = (size_t)(2 * t) * H_ + (size_t)h4 * 4;
    size_t o1 = (size_t)(2 * t + 1) * H_ + (size_t)h4 * 4;

    float4 a0 = make_float4(0.f, 0.f, 0.f, 0.f);
    float4 a1 = make_float4(0.f, 0.f, 0.f, 0.f);
#pragma unroll
    for (int s = 0; s < SPLITK; s++) {   // fixed order -> deterministic
        const float* p = g_part + (size_t)s * A_ * H_;
        float4 v0 = *(const float4*)(p + o0);
        float4 v1 = *(const float4*)(p + o1);
        a0.x += v0.x; a0.y += v0.y; a0.z += v0.z; a0.w += v0.w;
        a1.x += v1.x; a1.y += v1.y; a1.z += v1.z; a1.w += v1.w;
    }
    float4 o;
    o.x = w0 * a0.x + w1 * a1.x;
    o.y = w0 * a0.y + w1 * a1.y;
    o.z = w0 * a0.z + w1 * a1.z;
    o.w = w0 * a0.w + w1 * a1.w;
    *(float4*)&out[(size_t)t * H_ + (size_t)h4 * 4] = o;
}

extern "C" void kernel_launch(void* const* d_in, const int* in_sizes, int n_in,
                              void* d_out, int out_size) {
    const float* x   = (const float*)d_in[0];   // [512, 2048]
    const float* rl  = (const float*)d_in[1];   // [512, 8]
    const float* w13 = (const float*)d_in[2];   // [8, 11264, 2048]
    const float* w2  = (const float*)d_in[3];   // [8, 2048, 5632]
    float* out = (float*)d_out;                 // [512, 2048]
    (void)in_sizes; (void)n_in; (void)out_size;

    cudaFuncSetAttribute(gemm1_fused, cudaFuncAttributeMaxDynamicSharedMemorySize, G1_SMEM);
    cudaFuncSetAttribute(gemm2_tc,    cudaFuncAttributeMaxDynamicSharedMemorySize, G2_SMEM);

    xcvt_kernel<<<(T_ * H_ / 2) / 256, 256>>>(x);
    route_kernel<<<1, T_>>>(rl);
    // GEMM1 fused: grid.y = 4 covers worst case (512 tokens on one expert)
    gemm1_fused<<<dim3(I_ / 64, 4, E_), 256, G1_SMEM>>>(w13);
    // GEMM2 split-K: z = e*4 + sk
    gemm2_tc<<<dim3(H_ / 128, 4, E_ * SPLITK), 256, G2_SMEM>>>(w2);
    combine_kernel<<<(T_ * H_ / 4) / 512, 512>>>(out);
}

// round 9
// speedup vs baseline: 4.0530x; 1.0319x over previous
#include <cuda_runtime.h>
#include <cuda_fp16.h>
#include <cstdint>
#include <math.h>

// Problem constants
#define T_ 512
#define E_ 8
#define H_ 2048
#define I_ 5632
#define A_ (2 * T_)   // 1024 token-expert assignments (top_k = 2)
#define SPLITK 4
#define K2_PER (I_ / SPLITK)   // 1408

// ---------------- scratch (device globals; no allocation allowed) ----------------
__device__ __half g_xh[(size_t)T_ * H_];            // x converted to fp16
__device__ __half g_acth[(size_t)A_ * I_];          // SwiGLU activations fp16, perm order
__device__ float  g_part[(size_t)SPLITK * A_ * H_]; // split-K partials of down-proj
__device__ int    g_perm[A_];                       // assignment ids grouped by expert
__device__ int    g_offs[E_ + 1];                   // expert segment offsets
__device__ float  g_aw[A_];                         // renormalized top-2 weights

// ---------------- helpers ----------------
__device__ __forceinline__ uint32_t pack_h2(float2 v) {  // {lo=v.x, hi=v.y} as f16x2
    uint32_t r;
    asm("cvt.rn.f16x2.f32 %0, %1, %2;" : "=r"(r) : "f"(v.y), "f"(v.x));
    return r;
}
__device__ __forceinline__ void mma_f16(float* d, const uint32_t* a, const uint32_t* b) {
    asm volatile(
        "mma.sync.aligned.m16n8k16.row.col.f32.f16.f16.f32 "
        "{%0,%1,%2,%3}, {%4,%5,%6,%7}, {%8,%9}, {%0,%1,%2,%3};"
        : "+f"(d[0]), "+f"(d[1]), "+f"(d[2]), "+f"(d[3])
        : "r"(a[0]), "r"(a[1]), "r"(a[2]), "r"(a[3]), "r"(b[0]), "r"(b[1]));
}
__device__ __forceinline__ uint32_t smem_u32(const void* p) {
    return (uint32_t)__cvta_generic_to_shared(p);
}
#define CP_ASYNC16(dst, src) \
    asm volatile("cp.async.cg.shared.global [%0], [%1], 16;" :: "r"(dst), "l"(src))
#define CP_COMMIT() asm volatile("cp.async.commit_group;" ::: "memory")
#define CP_WAIT(n)  asm volatile("cp.async.wait_group %0;" :: "n"(n) : "memory")

// swizzled byte offset inside a (rows x 32-float) fp32 tile: 128B rows, 16B chunk XOR
__device__ __forceinline__ uint32_t tswz(int row, int k) {
    return (uint32_t)(row * 128 + (((k >> 2) ^ (row & 7)) << 4) + ((k & 3) << 2));
}
// load adjacent fp32 pair (k, k+1), k even — always within one 16B chunk
__device__ __forceinline__ float2 lds2(const char* base, int row, int k) {
    return *(const float2*)(base + tswz(row, k));
}

// fp16 A tile: 128 rows x 32 halves (64B data), padded row stride 80B (conflict-free)
#define AROW 80

// Unified stage geometry: A fp16 10240B | B fp32 16384B = 26624B
#define STG 26624
#define S1 4
#define S2 4
#define G1_SMEM (S1 * STG + 512)
#define G2_SMEM (S2 * STG + 512)

// ---------------- x -> fp16 ----------------
__global__ void xcvt_kernel(const float* __restrict__ x) {
    int i = blockIdx.x * blockDim.x + threadIdx.x;   // over T_*H_/2 half2
    float2 v = *(const float2*)&x[2 * i];
    *(uint32_t*)&g_xh[2 * i] = pack_h2(v);
}

// ---------------- routing ----------------
__global__ void route_kernel(const float* __restrict__ logits) {
    __shared__ unsigned char s_e[A_];
    __shared__ int s_cnt[E_];
    __shared__ int s_off[E_ + 1];

    int t = threadIdx.x;
    if (t < E_) s_cnt[t] = 0;
    __syncthreads();

    float l[E_];
#pragma unroll
    for (int e = 0; e < E_; e++) l[e] = logits[t * E_ + e];

    int e0 = 0;
#pragma unroll
    for (int e = 1; e < E_; e++) if (l[e] > l[e0]) e0 = e;
    int e1 = (e0 == 0) ? 1 : 0;
#pragma unroll
    for (int e = 0; e < E_; e++) if (e != e0 && l[e] > l[e1]) e1 = e;

    float p1 = __expf(l[e1] - l[e0]);
    float inv = 1.0f / (1.0f + p1);
    g_aw[2 * t + 0] = inv;
    g_aw[2 * t + 1] = p1 * inv;

    s_e[2 * t + 0] = (unsigned char)e0;
    s_e[2 * t + 1] = (unsigned char)e1;
    atomicAdd(&s_cnt[e0], 1);
    atomicAdd(&s_cnt[e1], 1);
    __syncthreads();

    if (t == 0) {
        int acc = 0;
        for (int e = 0; e < E_; e++) { s_off[e] = acc; acc += s_cnt[e]; }
        s_off[E_] = acc;
        for (int e = 0; e <= E_; e++) g_offs[e] = s_off[e];
    }
    __syncthreads();

#pragma unroll
    for (int k = 0; k < 2; k++) {
        int a = 2 * t + k;
        int e = s_e[a];
        int rank = 0;
        for (int b = 0; b < a; b++) rank += (s_e[b] == e) ? 1 : 0;
        g_perm[s_off[e] + rank] = a;
    }
}

// =================================================================================
// GEMM1 fused: act[m, i0..i0+64) = silu(x@Wg^T)*(x@Wu^T).
// B smem rows INTERLEAVED: row 2j = gate(i0+j), row 2j+1 = up(i0+j)  ==> the
// m16n8 accumulator pair (d[2rr], d[2rr+1]) is (gate_j, up_j) in-register.
// CTA: M=128 x N=128(B rows). 8 warps = 2M x 4N, warp 64x32. 4-stage cp.async.
// =================================================================================
__global__ __launch_bounds__(256, 2)
void gemm1_fused(const float* __restrict__ w13)
{
    constexpr int NS = H_ / 32;   // 64 stages

    extern __shared__ char sm[];
    int* s_row = (int*)(sm + S1 * STG);

    const int e = blockIdx.z;
    const int base = g_offs[e];
    const int cnt = g_offs[e + 1] - base;
    const int m0 = blockIdx.y * 128;
    if (m0 >= cnt) return;
    const int i0 = blockIdx.x * 64;

    const int tid = threadIdx.x;
    const int wid = tid >> 5, lid = tid & 31;
    const int gid = lid >> 2, tig = lid & 3;
    const int wm = wid & 1, wn = wid >> 1;   // 2M x 4N

    if (tid < 128) {
        int m = m0 + tid;
        int mm = (m < cnt) ? m : 0;
        s_row[tid] = g_perm[base + mm] >> 1;
    }
    __syncthreads();

    // A: 512 16B-chunks -> 2/thread.  B: 1024 chunks -> 4/thread (interleaved rows).
    const char* ap[2]; uint32_t soA[2];
    const float* bp[4]; uint32_t soB[4];
#pragma unroll
    for (int t = 0; t < 2; t++) {
        int idx = t * 256 + tid;
        int row = idx >> 2, q = idx & 3;
        soA[t] = (uint32_t)(row * AROW + q * 16);
        ap[t] = (const char*)(g_xh + (size_t)s_row[row] * H_) + q * 16;
    }
#pragma unroll
    for (int t = 0; t < 4; t++) {
        int idx = t * 256 + tid;
        int row = idx >> 3, q = idx & 7;   // smem row 0..127
        soB[t] = (uint32_t)(row * 128 + ((q ^ (row & 7)) << 4));
        int ii = i0 + (row >> 1) + ((row & 1) ? I_ : 0);   // gate/up interleave
        bp[t] = w13 + ((size_t)e * (2 * I_) + (size_t)ii) * H_ + q * 4;
    }

    const uint32_t smbase = smem_u32(sm);
    auto issue = [&](int stage) {
        uint32_t ab = smbase + (uint32_t)(stage % S1) * STG;
        uint32_t bb = ab + 10240;
#pragma unroll
        for (int t = 0; t < 2; t++) { CP_ASYNC16(ab + soA[t], ap[t]); ap[t] += 64; }
#pragma unroll
        for (int t = 0; t < 4; t++) { CP_ASYNC16(bb + soB[t], bp[t]); bp[t] += 32; }
    };

#pragma unroll
    for (int p = 0; p < S1 - 1; p++) { issue(p); CP_COMMIT(); }

    float c[4][4][4] = {};

    for (int s = 0; s < NS; s++) {
        CP_WAIT(S1 - 2);
        __syncthreads();
        if (s + S1 - 1 < NS) issue(s + S1 - 1);
        CP_COMMIT();

        const char* A = sm + (s % S1) * STG;
        const char* B = A + 10240;
#pragma unroll
        for (int kt = 0; kt < 2; kt++) {
            uint32_t af[4][4], bf[4][2];
#pragma unroll
            for (int mt = 0; mt < 4; mt++) {
                int rbase = wm * 64 + mt * 16 + gid;
                const char* p0 = A + rbase * AROW + kt * 32 + tig * 4;
                af[mt][0] = *(const uint32_t*)(p0);
                af[mt][1] = *(const uint32_t*)(p0 + 8 * AROW);
                af[mt][2] = *(const uint32_t*)(p0 + 16);
                af[mt][3] = *(const uint32_t*)(p0 + 8 * AROW + 16);
            }
            const int k0 = kt * 16 + 2 * tig;
#pragma unroll
            for (int nt = 0; nt < 4; nt++) {
                int n = wn * 32 + nt * 8 + gid;
                bf[nt][0] = pack_h2(lds2(B, n, k0));
                bf[nt][1] = pack_h2(lds2(B, n, k0 + 8));
            }
#pragma unroll
            for (int mt = 0; mt < 4; mt++)
#pragma unroll
                for (int nt = 0; nt < 4; nt++)
                    mma_f16(c[mt][nt], af[mt], bf[nt]);
        }
    }

    // epilogue: (d0,d1) = (gate_j, up_j), j = wn*16 + nt*4 + tig
#pragma unroll
    for (int mt = 0; mt < 4; mt++) {
#pragma unroll
        for (int rr = 0; rr < 2; rr++) {
            int m = m0 + wm * 64 + mt * 16 + gid + rr * 8;
            if (m < cnt) {
                __half* op = g_acth + (size_t)(base + m) * I_ + (size_t)(i0 + wn * 16 + tig);
#pragma unroll
                for (int nt = 0; nt < 4; nt++) {
                    float g = c[mt][nt][2 * rr];
                    float u = c[mt][nt][2 * rr + 1];
                    op[nt * 4] = __float2half((g / (1.0f + __expf(-g))) * u);
                }
            }
        }
    }
}

// =================================================================================
// GEMM2 (split-K=4): part[sk][a, h0..h0+128) = act_fp16 @ w2^T.
// CTA: M=128 x N=128, 8 warps = 2M x 4N (64x32/warp). K range 1408 (44 stages).
// =================================================================================
__global__ __launch_bounds__(256, 2)
void gemm2_tc(const float* __restrict__ w2)
{
    constexpr int NS = K2_PER / 32;   // 44 stages

    extern __shared__ char sm[];
    int* s_row = (int*)(sm + S2 * STG);

    const int e  = blockIdx.z >> 2;
    const int sk = blockIdx.z & 3;
    const int base = g_offs[e];
    const int cnt = g_offs[e + 1] - base;
    const int m0 = blockIdx.y * 128;
    if (m0 >= cnt) return;
    const int n0 = blockIdx.x * 128;
    const int koff = sk * K2_PER;

    const int tid = threadIdx.x;
    const int wid = tid >> 5, lid = tid & 31;
    const int gid = lid >> 2, tig = lid & 3;
    const int wm = wid & 1, wn = wid >> 1;   // 2M x 4N

    if (tid < 128) {
        int m = m0 + tid;
        s_row[tid] = base + ((m < cnt) ? m : 0);
    }
    __syncthreads();

    const char* ap[2]; uint32_t soA[2];
    const float* bp[4]; uint32_t soB[4];
#pragma unroll
    for (int t = 0; t < 2; t++) {
        int idx = t * 256 + tid;
        int row = idx >> 2, q = idx & 3;
        soA[t] = (uint32_t)(row * AROW + q * 16);
        ap[t] = (const char*)(g_acth + (size_t)s_row[row] * I_ + koff) + q * 16;
    }
#pragma unroll
    for (int t = 0; t < 4; t++) {
        int idx = t * 256 + tid;
        int row = idx >> 3, q = idx & 7;
        soB[t] = (uint32_t)(row * 128 + ((q ^ (row & 7)) << 4));
        bp[t] = w2 + ((size_t)e * H_ + (size_t)(n0 + row)) * I_ + koff + q * 4;
    }

    const uint32_t smbase = smem_u32(sm);
    auto issue = [&](int stage) {
        uint32_t ab = smbase + (uint32_t)(stage % S2) * STG;
        uint32_t bb = ab + 10240;
#pragma unroll
        for (int t = 0; t < 2; t++) { CP_ASYNC16(ab + soA[t], ap[t]); ap[t] += 64; }
#pragma unroll
        for (int t = 0; t < 4; t++) { CP_ASYNC16(bb + soB[t], bp[t]); bp[t] += 32; }
    };

#pragma unroll
    for (int p = 0; p < S2 - 1; p++) { issue(p); CP_COMMIT(); }

    float c[4][4][4] = {};

    for (int s = 0; s < NS; s++) {
        CP_WAIT(S2 - 2);
        __syncthreads();
        if (s + S2 - 1 < NS) issue(s + S2 - 1);
        CP_COMMIT();

        const char* A = sm + (s % S2) * STG;
        const char* B = A + 10240;
#pragma unroll
        for (int kt = 0; kt < 2; kt++) {
            uint32_t af[4][4], bf[4][2];
#pragma unroll
            for (int mt = 0; mt < 4; mt++) {
                int rbase = wm * 64 + mt * 16 + gid;
                const char* p0 = A + rbase * AROW + kt * 32 + tig * 4;
                af[mt][0] = *(const uint32_t*)(p0);
                af[mt][1] = *(const uint32_t*)(p0 + 8 * AROW);
                af[mt][2] = *(const uint32_t*)(p0 + 16);
                af[mt][3] = *(const uint32_t*)(p0 + 8 * AROW + 16);
            }
            const int k0 = kt * 16 + 2 * tig;
#pragma unroll
            for (int nt = 0; nt < 4; nt++) {
                int n = wn * 32 + nt * 8 + gid;
                bf[nt][0] = pack_h2(lds2(B, n, k0));
                bf[nt][1] = pack_h2(lds2(B, n, k0 + 8));
            }
#pragma unroll
            for (int mt = 0; mt < 4; mt++)
#pragma unroll
                for (int nt = 0; nt < 4; nt++)
                    mma_f16(c[mt][nt], af[mt], bf[nt]);
        }
    }

    // epilogue: write split partial (assignment-id rows)
    float* part = g_part + (size_t)sk * A_ * H_;
#pragma unroll
    for (int mt = 0; mt < 4; mt++) {
#pragma unroll
        for (int rr = 0; rr < 2; rr++) {
            int m = m0 + wm * 64 + mt * 16 + gid + rr * 8;
            if (m < cnt) {
                int orow = g_perm[base + m];
                float* op = part + (size_t)orow * H_ + (size_t)(n0 + wn * 32) + 2 * tig;
#pragma unroll
                for (int nt = 0; nt < 4; nt++) {
                    float2 v = make_float2(c[mt][nt][2 * rr], c[mt][nt][2 * rr + 1]);
                    *(float2*)(op + nt * 8) = v;
                }
            }
        }
    }
}

// ---------------- combine: out[t,h] = sum_k aw * sum_s part[s][2t+k][h] -----------
__global__ void combine_kernel(float* __restrict__ out) {
    int idx = blockIdx.x * blockDim.x + threadIdx.x;
    int t  = idx >> 9;
    int h4 = idx & 511;
    float w0 = g_aw[2 * t];
    float w1 = g_aw[2 * t + 1];
    size_t o0 = (size_t)(2 * t) * H_ + (size_t)h4 * 4;
    size_t o1 = (size_t)(2 * t + 1) * H_ + (size_t)h4 * 4;

    float4 a0 = make_float4(0.f, 0.f, 0.f, 0.f);
    float4 a1 = make_float4(0.f, 0.f, 0.f, 0.f);
#pragma unroll
    for (int s = 0; s < SPLITK; s++) {   // fixed order -> deterministic
        const float* p = g_part + (size_t)s * A_ * H_;
        float4 v0 = *(const float4*)(p + o0);
        float4 v1 = *(const float4*)(p + o1);
        a0.x += v0.x; a0.y += v0.y; a0.z += v0.z; a0.w += v0.w;
        a1.x += v1.x; a1.y += v1.y; a1.z += v1.z; a1.w += v1.w;
    }
    float4 o;
    o.x = w0 * a0.x + w1 * a1.x;
    o.y = w0 * a0.y + w1 * a1.y;
    o.z = w0 * a0.z + w1 * a1.z;
    o.w = w0 * a0.w + w1 * a1.w;
    *(float4*)&out[(size_t)t * H_ + (size_t)h4 * 4] = o;
}

extern "C" void kernel_launch(void* const* d_in, const int* in_sizes, int n_in,
                              void* d_out, int out_size) {
    const float* x   = (const float*)d_in[0];   // [512, 2048]
    const float* rl  = (const float*)d_in[1];   // [512, 8]
    const float* w13 = (const float*)d_in[2];   // [8, 11264, 2048]
    const float* w2  = (const float*)d_in[3];   // [8, 2048, 5632]
    float* out = (float*)d_out;                 // [512, 2048]
    (void)in_sizes; (void)n_in; (void)out_size;

    cudaFuncSetAttribute(gemm1_fused, cudaFuncAttributeMaxDynamicSharedMemorySize, G1_SMEM);
    cudaFuncSetAttribute(gemm2_tc,    cudaFuncAttributeMaxDynamicSharedMemorySize, G2_SMEM);

    xcvt_kernel<<<(T_ * H_ / 2) / 256, 256>>>(x);
    route_kernel<<<1, T_>>>(rl);
    // GEMM1 fused: 88 i-tiles x 4 M-blocks x 8 experts
    gemm1_fused<<<dim3(I_ / 64, 4, E_), 256, G1_SMEM>>>(w13);
    // GEMM2 split-K: z = e*4 + sk
    gemm2_tc<<<dim3(H_ / 128, 4, E_ * SPLITK), 256, G2_SMEM>>>(w2);
    combine_kernel<<<(T_ * H_ / 4) / 512, 512>>>(out);
}

// round 10
// speedup vs baseline: 4.4716x; 1.1033x over previous
#include <cuda_runtime.h>
#include <cuda_fp16.h>
#include <cstdint>
#include <math.h>

// Problem constants
#define T_ 512
#define E_ 8
#define H_ 2048
#define I_ 5632
#define A_ (2 * T_)   // 1024 token-expert assignments (top_k = 2)
#define SPLITK 4
#define K2_PER (I_ / SPLITK)   // 1408

// ---------------- scratch (device globals; no allocation allowed) ----------------
__device__ __half g_xh[(size_t)T_ * H_];            // x converted to fp16
__device__ __half g_acth[(size_t)A_ * I_];          // SwiGLU activations fp16, perm order
__device__ float  g_part[(size_t)SPLITK * A_ * H_]; // split-K partials of down-proj
__device__ int    g_perm[A_];                       // assignment ids grouped by expert
__device__ int    g_offs[E_ + 1];                   // expert segment offsets
__device__ float  g_aw[A_];                         // renormalized top-2 weights

// ---------------- helpers ----------------
__device__ __forceinline__ uint32_t pack_h2(float2 v) {  // {lo=v.x, hi=v.y} as f16x2
    uint32_t r;
    asm("cvt.rn.f16x2.f32 %0, %1, %2;" : "=r"(r) : "f"(v.y), "f"(v.x));
    return r;
}
__device__ __forceinline__ void mma_f16(float* d, const uint32_t* a, const uint32_t* b) {
    asm volatile(
        "mma.sync.aligned.m16n8k16.row.col.f32.f16.f16.f32 "
        "{%0,%1,%2,%3}, {%4,%5,%6,%7}, {%8,%9}, {%0,%1,%2,%3};"
        : "+f"(d[0]), "+f"(d[1]), "+f"(d[2]), "+f"(d[3])
        : "r"(a[0]), "r"(a[1]), "r"(a[2]), "r"(a[3]), "r"(b[0]), "r"(b[1]));
}
__device__ __forceinline__ void ldsm_x4(uint32_t* r, uint32_t addr) {
    asm volatile("ldmatrix.sync.aligned.m8n8.x4.shared.b16 {%0,%1,%2,%3}, [%4];"
                 : "=r"(r[0]), "=r"(r[1]), "=r"(r[2]), "=r"(r[3]) : "r"(addr));
}
__device__ __forceinline__ uint32_t smem_u32(const void* p) {
    return (uint32_t)__cvta_generic_to_shared(p);
}
#define CP_ASYNC16(dst, src) \
    asm volatile("cp.async.cg.shared.global [%0], [%1], 16;" :: "r"(dst), "l"(src))
#define CP_COMMIT() asm volatile("cp.async.commit_group;" ::: "memory")
#define CP_WAIT(n)  asm volatile("cp.async.wait_group %0;" :: "n"(n) : "memory")

// B tile swizzle: chunk q of row n stored at position q ^ ((n&3)<<1).
// Fragment reads (LDS.64) become conflict-free per 16-lane phase (bit0 from k-step,
// bits1-2 from gid&3).
__device__ __forceinline__ uint32_t tswz(int row, int k) {
    return (uint32_t)(row * 128 + (((k >> 2) ^ ((row & 3) << 1)) << 4) + ((k & 3) << 2));
}
// load adjacent fp32 pair (k, k+1), k even — always within one 16B chunk
__device__ __forceinline__ float2 lds2(const char* base, int row, int k) {
    return *(const float2*)(base + tswz(row, k));
}

// fp16 A tile: 128 rows x 32 halves (64B data), padded row stride 80B (conflict-free)
#define AROW 80

// Unified stage geometry: A fp16 10240B | B fp32 16384B = 26624B
#define STG 26624
#define S1 4
#define S2 4
#define G1_SMEM (S1 * STG + 512)
#define G2_SMEM (S2 * STG + 512)

// ---------------- x -> fp16 ----------------
__global__ void xcvt_kernel(const float* __restrict__ x) {
    int i = blockIdx.x * blockDim.x + threadIdx.x;   // over T_*H_/2 half2
    float2 v = *(const float2*)&x[2 * i];
    *(uint32_t*)&g_xh[2 * i] = pack_h2(v);
}

// ---------------- routing ----------------
__global__ void route_kernel(const float* __restrict__ logits) {
    __shared__ unsigned char s_e[A_];
    __shared__ int s_cnt[E_];
    __shared__ int s_off[E_ + 1];

    int t = threadIdx.x;
    if (t < E_) s_cnt[t] = 0;
    __syncthreads();

    float l[E_];
#pragma unroll
    for (int e = 0; e < E_; e++) l[e] = logits[t * E_ + e];

    int e0 = 0;
#pragma unroll
    for (int e = 1; e < E_; e++) if (l[e] > l[e0]) e0 = e;
    int e1 = (e0 == 0) ? 1 : 0;
#pragma unroll
    for (int e = 0; e < E_; e++) if (e != e0 && l[e] > l[e1]) e1 = e;

    float p1 = __expf(l[e1] - l[e0]);
    float inv = 1.0f / (1.0f + p1);
    g_aw[2 * t + 0] = inv;
    g_aw[2 * t + 1] = p1 * inv;

    s_e[2 * t + 0] = (unsigned char)e0;
    s_e[2 * t + 1] = (unsigned char)e1;
    atomicAdd(&s_cnt[e0], 1);
    atomicAdd(&s_cnt[e1], 1);
    __syncthreads();

    if (t == 0) {
        int acc = 0;
        for (int e = 0; e < E_; e++) { s_off[e] = acc; acc += s_cnt[e]; }
        s_off[E_] = acc;
        for (int e = 0; e <= E_; e++) g_offs[e] = s_off[e];
    }
    __syncthreads();

#pragma unroll
    for (int k = 0; k < 2; k++) {
        int a = 2 * t + k;
        int e = s_e[a];
        int rank = 0;
        for (int b = 0; b < a; b++) rank += (s_e[b] == e) ? 1 : 0;
        g_perm[s_off[e] + rank] = a;
    }
}

// =================================================================================
// GEMM1 fused: act[m, i0..i0+64) = silu(x@Wg^T)*(x@Wu^T).
// B smem rows INTERLEAVED: row 2j = gate(i0+j), row 2j+1 = up(i0+j)  ==> the
// m16n8 accumulator pair (d[2rr], d[2rr+1]) is (gate_j, up_j) in-register.
// CTA: M=128 x N=128(B rows). 8 warps = 2M x 4N, warp 64x32. 4-stage cp.async.
// A fragments via ldmatrix; B via conflict-free-swizzle LDS.64 + cvt.
// =================================================================================
__global__ __launch_bounds__(256, 2)
void gemm1_fused(const float* __restrict__ w13)
{
    constexpr int NS = H_ / 32;   // 64 stages

    extern __shared__ char sm[];
    int* s_row = (int*)(sm + S1 * STG);

    const int e = blockIdx.z;
    const int base = g_offs[e];
    const int cnt = g_offs[e + 1] - base;
    const int m0 = blockIdx.y * 128;
    if (m0 >= cnt) return;
    const int i0 = blockIdx.x * 64;

    const int tid = threadIdx.x;
    const int wid = tid >> 5, lid = tid & 31;
    const int gid = lid >> 2, tig = lid & 3;
    const int wm = wid & 1, wn = wid >> 1;   // 2M x 4N

    if (tid < 128) {
        int m = m0 + tid;
        int mm = (m < cnt) ? m : 0;
        s_row[tid] = g_perm[base + mm] >> 1;
    }
    __syncthreads();

    // ldmatrix lane offset within the A tile (rows + 16B k-chunk select)
    const uint32_t lmoff =
        (uint32_t)((wm * 64 + (lid & 7) + ((lid >> 3) & 1) * 8) * AROW + ((lid >> 4) & 1) * 16);

    // A: 512 16B-chunks -> 2/thread.  B: 1024 chunks -> 4/thread (interleaved rows).
    const char* ap[2]; uint32_t soA[2];
    const float* bp[4]; uint32_t soB[4];
#pragma unroll
    for (int t = 0; t < 2; t++) {
        int idx = t * 256 + tid;
        int row = idx >> 2, q = idx & 3;
        soA[t] = (uint32_t)(row * AROW + q * 16);
        ap[t] = (const char*)(g_xh + (size_t)s_row[row] * H_) + q * 16;
    }
#pragma unroll
    for (int t = 0; t < 4; t++) {
        int idx = t * 256 + tid;
        int row = idx >> 3, q = idx & 7;   // smem row 0..127
        soB[t] = (uint32_t)(row * 128 + ((q ^ ((row & 3) << 1)) << 4));
        int ii = i0 + (row >> 1) + ((row & 1) ? I_ : 0);   // gate/up interleave
        bp[t] = w13 + ((size_t)e * (2 * I_) + (size_t)ii) * H_ + q * 4;
    }

    const uint32_t smbase = smem_u32(sm);
    auto issue = [&](int stage) {
        uint32_t ab = smbase + (uint32_t)(stage % S1) * STG;
        uint32_t bb = ab + 10240;
#pragma unroll
        for (int t = 0; t < 2; t++) { CP_ASYNC16(ab + soA[t], ap[t]); ap[t] += 64; }
#pragma unroll
        for (int t = 0; t < 4; t++) { CP_ASYNC16(bb + soB[t], bp[t]); bp[t] += 32; }
    };

#pragma unroll
    for (int p = 0; p < S1 - 1; p++) { issue(p); CP_COMMIT(); }

    float c[4][4][4] = {};

    for (int s = 0; s < NS; s++) {
        CP_WAIT(S1 - 2);
        __syncthreads();
        if (s + S1 - 1 < NS) issue(s + S1 - 1);
        CP_COMMIT();

        const uint32_t Asm = smbase + (uint32_t)(s % S1) * STG;
        const char* B = sm + (s % S1) * STG + 10240;
#pragma unroll
        for (int kt = 0; kt < 2; kt++) {
            uint32_t af[4][4], bf[4][2];
#pragma unroll
            for (int mt = 0; mt < 4; mt++)
                ldsm_x4(af[mt], Asm + lmoff + (uint32_t)(mt * 16 * AROW + kt * 32));
            const int k0 = kt * 16 + 2 * tig;
#pragma unroll
            for (int nt = 0; nt < 4; nt++) {
                int n = wn * 32 + nt * 8 + gid;
                bf[nt][0] = pack_h2(lds2(B, n, k0));
                bf[nt][1] = pack_h2(lds2(B, n, k0 + 8));
            }
#pragma unroll
            for (int mt = 0; mt < 4; mt++)
#pragma unroll
                for (int nt = 0; nt < 4; nt++)
                    mma_f16(c[mt][nt], af[mt], bf[nt]);
        }
    }

    // epilogue: (d0,d1) = (gate_j, up_j), j = wn*16 + nt*4 + tig
#pragma unroll
    for (int mt = 0; mt < 4; mt++) {
#pragma unroll
        for (int rr = 0; rr < 2; rr++) {
            int m = m0 + wm * 64 + mt * 16 + gid + rr * 8;
            if (m < cnt) {
                __half* op = g_acth + (size_t)(base + m) * I_ + (size_t)(i0 + wn * 16 + tig);
#pragma unroll
                for (int nt = 0; nt < 4; nt++) {
                    float g = c[mt][nt][2 * rr];
                    float u = c[mt][nt][2 * rr + 1];
                    op[nt * 4] = __float2half((g / (1.0f + __expf(-g))) * u);
                }
            }
        }
    }
}

// =================================================================================
// GEMM2 (split-K=4): part[sk][a, h0..h0+128) = act_fp16 @ w2^T.
// CTA: M=128 x N=128, 8 warps = 2M x 4N (64x32/warp). K range 1408 (44 stages).
// =================================================================================
__global__ __launch_bounds__(256, 2)
void gemm2_tc(const float* __restrict__ w2)
{
    constexpr int NS = K2_PER / 32;   // 44 stages

    extern __shared__ char sm[];
    int* s_row = (int*)(sm + S2 * STG);

    const int e  = blockIdx.z >> 2;
    const int sk = blockIdx.z & 3;
    const int base = g_offs[e];
    const int cnt = g_offs[e + 1] - base;
    const int m0 = blockIdx.y * 128;
    if (m0 >= cnt) return;
    const int n0 = blockIdx.x * 128;
    const int koff = sk * K2_PER;

    const int tid = threadIdx.x;
    const int wid = tid >> 5, lid = tid & 31;
    const int gid = lid >> 2, tig = lid & 3;
    const int wm = wid & 1, wn = wid >> 1;   // 2M x 4N

    if (tid < 128) {
        int m = m0 + tid;
        s_row[tid] = base + ((m < cnt) ? m : 0);
    }
    __syncthreads();

    const uint32_t lmoff =
        (uint32_t)((wm * 64 + (lid & 7) + ((lid >> 3) & 1) * 8) * AROW + ((lid >> 4) & 1) * 16);

    const char* ap[2]; uint32_t soA[2];
    const float* bp[4]; uint32_t soB[4];
#pragma unroll
    for (int t = 0; t < 2; t++) {
        int idx = t * 256 + tid;
        int row = idx >> 2, q = idx & 3;
        soA[t] = (uint32_t)(row * AROW + q * 16);
        ap[t] = (const char*)(g_acth + (size_t)s_row[row] * I_ + koff) + q * 16;
    }
#pragma unroll
    for (int t = 0; t < 4; t++) {
        int idx = t * 256 + tid;
        int row = idx >> 3, q = idx & 7;
        soB[t] = (uint32_t)(row * 128 + ((q ^ ((row & 3) << 1)) << 4));
        bp[t] = w2 + ((size_t)e * H_ + (size_t)(n0 + row)) * I_ + koff + q * 4;
    }

    const uint32_t smbase = smem_u32(sm);
    auto issue = [&](int stage) {
        uint32_t ab = smbase + (uint32_t)(stage % S2) * STG;
        uint32_t bb = ab + 10240;
#pragma unroll
        for (int t = 0; t < 2; t++) { CP_ASYNC16(ab + soA[t], ap[t]); ap[t] += 64; }
#pragma unroll
        for (int t = 0; t < 4; t++) { CP_ASYNC16(bb + soB[t], bp[t]); bp[t] += 32; }
    };

#pragma unroll
    for (int p = 0; p < S2 - 1; p++) { issue(p); CP_COMMIT(); }

    float c[4][4][4] = {};

    for (int s = 0; s < NS; s++) {
        CP_WAIT(S2 - 2);
        __syncthreads();
        if (s + S2 - 1 < NS) issue(s + S2 - 1);
        CP_COMMIT();

        const uint32_t Asm = smbase + (uint32_t)(s % S2) * STG;
        const char* B = sm + (s % S2) * STG + 10240;
#pragma unroll
        for (int kt = 0; kt < 2; kt++) {
            uint32_t af[4][4], bf[4][2];
#pragma unroll
            for (int mt = 0; mt < 4; mt++)
                ldsm_x4(af[mt], Asm + lmoff + (uint32_t)(mt * 16 * AROW + kt * 32));
            const int k0 = kt * 16 + 2 * tig;
#pragma unroll
            for (int nt = 0; nt < 4; nt++) {
                int n = wn * 32 + nt * 8 + gid;
                bf[nt][0] = pack_h2(lds2(B, n, k0));
                bf[nt][1] = pack_h2(lds2(B, n, k0 + 8));
            }
#pragma unroll
            for (int mt = 0; mt < 4; mt++)
#pragma unroll
                for (int nt = 0; nt < 4; nt++)
                    mma_f16(c[mt][nt], af[mt], bf[nt]);
        }
    }

    // epilogue: write split partial (assignment-id rows)
    float* part = g_part + (size_t)sk * A_ * H_;
#pragma unroll
    for (int mt = 0; mt < 4; mt++) {
#pragma unroll
        for (int rr = 0; rr < 2; rr++) {
            int m = m0 + wm * 64 + mt * 16 + gid + rr * 8;
            if (m < cnt) {
                int orow = g_perm[base + m];
                float* op = part + (size_t)orow * H_ + (size_t)(n0 + wn * 32) + 2 * tig;
#pragma unroll
                for (int nt = 0; nt < 4; nt++) {
                    float2 v = make_float2(c[mt][nt][2 * rr], c[mt][nt][2 * rr + 1]);
                    *(float2*)(op + nt * 8) = v;
                }
            }
        }
    }
}

// ---------------- combine: out[t,h] = sum_k aw * sum_s part[s][2t+k][h] -----------
__global__ void combine_kernel(float* __restrict__ out) {
    int idx = blockIdx.x * blockDim.x + threadIdx.x;
    int t  = idx >> 9;
    int h4 = idx & 511;
    float w0 = g_aw[2 * t];
    float w1 = g_aw[2 * t + 1];
    size_t o0 = (size_t)(2 * t) * H_ + (size_t)h4 * 4;
    size_t o1 = (size_t)(2 * t + 1) * H_ + (size_t)h4 * 4;

    float4 a0 = make_float4(0.f, 0.f, 0.f, 0.f);
    float4 a1 = make_float4(0.f, 0.f, 0.f, 0.f);
#pragma unroll
    for (int s = 0; s < SPLITK; s++) {   // fixed order -> deterministic
        const float* p = g_part + (size_t)s * A_ * H_;
        float4 v0 = *(const float4*)(p + o0);
        float4 v1 = *(const float4*)(p + o1);
        a0.x += v0.x; a0.y += v0.y; a0.z += v0.z; a0.w += v0.w;
        a1.x += v1.x; a1.y += v1.y; a1.z += v1.z; a1.w += v1.w;
    }
    float4 o;
    o.x = w0 * a0.x + w1 * a1.x;
    o.y = w0 * a0.y + w1 * a1.y;
    o.z = w0 * a0.z + w1 * a1.z;
    o.w = w0 * a0.w + w1 * a1.w;
    *(float4*)&out[(size_t)t * H_ + (size_t)h4 * 4] = o;
}

extern "C" void kernel_launch(void* const* d_in, const int* in_sizes, int n_in,
                              void* d_out, int out_size) {
    const float* x   = (const float*)d_in[0];   // [512, 2048]
    const float* rl  = (const float*)d_in[1];   // [512, 8]
    const float* w13 = (const float*)d_in[2];   // [8, 11264, 2048]
    const float* w2  = (const float*)d_in[3];   // [8, 2048, 5632]
    float* out = (float*)d_out;                 // [512, 2048]
    (void)in_sizes; (void)n_in; (void)out_size;

    cudaFuncSetAttribute(gemm1_fused, cudaFuncAttributeMaxDynamicSharedMemorySize, G1_SMEM);
    cudaFuncSetAttribute(gemm2_tc,    cudaFuncAttributeMaxDynamicSharedMemorySize, G2_SMEM);

    xcvt_kernel<<<(T_ * H_ / 2) / 256, 256>>>(x);
    route_kernel<<<1, T_>>>(rl);
    // GEMM1 fused: 88 i-tiles x 4 M-blocks x 8 experts
    gemm1_fused<<<dim3(I_ / 64, 4, E_), 256, G1_SMEM>>>(w13);
    // GEMM2 split-K: z = e*4 + sk
    gemm2_tc<<<dim3(H_ / 128, 4, E_ * SPLITK), 256, G2_SMEM>>>(w2);
    combine_kernel<<<(T_ * H_ / 4) / 512, 512>>>(out);
}